// round 4
// baseline (speedup 1.0000x reference)
#include <cuda_runtime.h>
#include <cstdint>
#include <math.h>

#define NVOX 100000
#define CDIM 64
#define C4   256
#define KKTOT 343
#define TILE 256          // voxels per conv CTA
#define NT   256
#define CBLK 391          // ceil(NVOX/TILE)
#define PTILE 128         // voxels per pw CTA
#define PBLK 782          // ceil(NVOX/PTILE)
#define ASTR 68           // A smem row stride in floats (conflict-free)

// ---------------- static scratch ----------------
__device__ float g_x[(size_t)NVOX * CDIM];
__device__ float g_y[(size_t)NVOX * C4];
__device__ float g_wB[(size_t)KKTOT * CDIM * CDIM];   // B tiles in mma-fragment layout, tf32-rounded
__device__ float g_part1[CBLK * 8];
__device__ float g_part2[PBLK * 2 * C4];
__device__ float g_gx2[2 * C4];
__device__ float g_gn[4];
__device__ float g_sj[2 * C4];
__device__ float g_bterm[CDIM];

// ---------------- smem layout (bytes) ----------------
#define OFF_A0   0
#define OFF_A1   69632
#define OFF_B0   139264
#define OFF_B1   155648
#define OFF_SIDX 172032      // 256*7 ints
#define OFF_VL0  179200      // 256 ints
#define OFF_VL1  180224
#define OFF_BS   181248      // 256 ints
#define OFF_NV   182272      // 2 ints
#define CONV_SMEM 182400

__device__ __forceinline__ uint32_t f2tf32(float x) {
    uint32_t r;
    asm("cvt.rna.tf32.f32 %0, %1;" : "=r"(r) : "f"(x));
    return r;
}

__device__ __forceinline__ void mma_tf32(float c[4], uint32_t a0, uint32_t a1,
                                         uint32_t a2, uint32_t a3,
                                         uint32_t b0, uint32_t b1) {
    asm volatile(
        "mma.sync.aligned.m16n8k8.row.col.f32.tf32.tf32.f32 "
        "{%0,%1,%2,%3}, {%4,%5,%6,%7}, {%8,%9}, {%0,%1,%2,%3};"
        : "+f"(c[0]), "+f"(c[1]), "+f"(c[2]), "+f"(c[3])
        : "r"(a0), "r"(a1), "r"(a2), "r"(a3), "r"(b0), "r"(b1));
}

#define PBAR() asm volatile("bar.sync 1, 128;" ::: "memory")

// ================= prep: w_dw[k] -> B-fragment layout, tf32-rounded =================
// element (cin, cout): kstep=cin>>3, kk=cin&7, nt=cout>>3, nn=cout&7
// dst index = ((kstep*8+nt)*32 + nn*4 + (kk&3))*2 + (kk>>2)
__global__ void __launch_bounds__(NT) prep_wB(const float* __restrict__ w_dw) {
    const int k = blockIdx.x;
    const float* wk = w_dw + (size_t)k * 4096;
    float* dst = g_wB + (size_t)k * 4096;
    for (int t = threadIdx.x; t < 4096; t += NT) {
        int cin = t >> 6, cout = t & 63;
        int kstep = cin >> 3, kk = cin & 7;
        int nt = cout >> 3, nn = cout & 7;
        int idx = (((kstep * 8 + nt) * 32 + nn * 4 + (kk & 3)) << 1) + (kk >> 2);
        uint32_t v = f2tf32(wk[t]);
        dst[idx] = __uint_as_float(v);
    }
}

// ================= conv: warp-specialized tf32 mma.sync =================
__global__ void __launch_bounds__(NT, 1) conv_kernel(
    const float* __restrict__ feats,
    const float* __restrict__ b_dw,
    const int*   __restrict__ nbr,
    const int*   __restrict__ batch_ids)
{
    extern __shared__ __align__(16) unsigned char smraw[];
    float* A[2]  = { (float*)(smraw + OFF_A0), (float*)(smraw + OFF_A1) };
    float* B[2]  = { (float*)(smraw + OFF_B0), (float*)(smraw + OFF_B1) };
    int* sidx    = (int*)(smraw + OFF_SIDX);
    int* VL[2]   = { (int*)(smraw + OFF_VL0), (int*)(smraw + OFF_VL1) };
    int* bs      = (int*)(smraw + OFF_BS);
    int* nv      = (int*)(smraw + OFF_NV);

    const int tid  = threadIdx.x;
    const int lane = tid & 31;
    const int i0   = blockIdx.x * TILE;
    const bool isMMA = tid < 128;
    const int w    = tid >> 5;           // mma warps: 0..3
    const int ptid = tid - 128;          // producers: 0..127

    // zero both A buffers fully (TILE*ASTR floats each)
    {
        float4 z = make_float4(0.f, 0.f, 0.f, 0.f);
        float4* a0 = (float4*)A[0];
        float4* a1 = (float4*)A[1];
        for (int t = tid; t < TILE * ASTR / 4; t += NT) { a0[t] = z; a1[t] = z; }
    }
    if (tid < TILE) {
        int gi = i0 + tid;
        bs[tid] = (gi < NVOX) ? batch_ids[gi] : -1;
    }
    if (tid == 0) { nv[0] = 0; nv[1] = 0; }

    float acc[4][8][4];
    #pragma unroll
    for (int s = 0; s < 4; s++)
        #pragma unroll
        for (int n = 0; n < 8; n++)
            #pragma unroll
            for (int q = 0; q < 4; q++) acc[s][n][q] = 0.f;

    int mprev0 = 0, mprev1 = 0;
    __syncthreads();

    // ---- prologue: produce buffer 0 for k=0 ----
    if (!isMMA) {
        // stage sidx chunk for ks [0,7)
        for (int t = ptid; t < TILE * 7; t += 128) {
            int r = t / 7, j = t - r * 7;
            int gi = i0 + r;
            sidx[t] = (gi < NVOX) ? nbr[(long long)gi * KKTOT + j] : NVOX;
        }
        PBAR();
        for (int r = ptid; r < TILE; r += 128) {
            int n = sidx[r * 7];
            if (n < NVOX) {
                int slot = atomicAdd(&nv[0], 1);
                VL[0][slot] = (r << 17) | n;
            }
        }
        {   // B copy for k=0
            const float4* src = (const float4*)(g_wB);
            float4* dst = (float4*)B[0];
            for (int t = ptid; t < 1024; t += 128) dst[t] = src[t];
        }
        PBAR();
        int m = nv[0];
        mprev0 = m;
        for (int t = ptid; t < m * 16; t += 128) {
            int e = t >> 4, pc = t & 15;
            int u = VL[0][e];
            int v = u >> 17, n = u & 0x1FFFF;
            float4 fv = ((const float4*)feats)[(size_t)n * 16 + pc];
            float4 o;
            o.x = __uint_as_float(f2tf32(fv.x));
            o.y = __uint_as_float(f2tf32(fv.y));
            o.z = __uint_as_float(f2tf32(fv.z));
            o.w = __uint_as_float(f2tf32(fv.w));
            *(float4*)(A[0] + v * ASTR + pc * 4) = o;
        }
    }
    __syncthreads();

    // ---- main loop ----
    for (int k = 0; k < KKTOT; k++) {
        const int buf = k & 1;
        if (isMMA) {
            const float* Aw = A[buf] + ((w * 64 + (lane >> 2)) * ASTR + (lane & 3));
            const float2* Bf = (const float2*)B[buf];
            #pragma unroll
            for (int ks = 0; ks < 8; ks++) {
                uint32_t b0[8], b1[8];
                #pragma unroll
                for (int n = 0; n < 8; n++) {
                    float2 bv = Bf[(ks * 8 + n) * 32 + lane];
                    b0[n] = __float_as_uint(bv.x);
                    b1[n] = __float_as_uint(bv.y);
                }
                #pragma unroll
                for (int s = 0; s < 4; s++) {
                    const float* Ap = Aw + s * 16 * ASTR + ks * 8;
                    uint32_t a0 = __float_as_uint(Ap[0]);
                    uint32_t a1 = __float_as_uint(Ap[8 * ASTR]);
                    uint32_t a2 = __float_as_uint(Ap[4]);
                    uint32_t a3 = __float_as_uint(Ap[8 * ASTR + 4]);
                    #pragma unroll
                    for (int n = 0; n < 8; n++)
                        mma_tf32(acc[s][n], a0, a1, a2, a3, b0[n], b1[n]);
                }
            }
        } else if (k + 1 < KKTOT) {
            const int kk = k + 1;
            const int nb = buf ^ 1;
            int* vl = VL[nb];
            float* Ab = A[nb];
            // 1) stage sidx for new 7-chunk
            if ((kk % 7) == 0) {
                for (int t = ptid; t < TILE * 7; t += 128) {
                    int r = t / 7, j = t - r * 7;
                    int gi = i0 + r;
                    sidx[t] = (gi < NVOX) ? nbr[(long long)gi * KKTOT + kk + j] : NVOX;
                }
            }
            // 2) zero rows used last time in this buffer
            {
                const int mz = (nb == 0) ? mprev0 : mprev1;
                float4 z = make_float4(0.f, 0.f, 0.f, 0.f);
                for (int t = ptid; t < mz * 16; t += 128) {
                    int e = t >> 4, pc = t & 15;
                    int v = vl[e] >> 17;
                    *(float4*)(Ab + v * ASTR + pc * 4) = z;
                }
            }
            if (ptid == 0) nv[nb] = 0;
            PBAR();
            // 3) compact + B copy
            for (int r = ptid; r < TILE; r += 128) {
                int n = sidx[r * 7 + (kk % 7)];
                if (n < NVOX) {
                    int slot = atomicAdd(&nv[nb], 1);
                    vl[slot] = (r << 17) | n;
                }
            }
            {
                const float4* src = (const float4*)(g_wB + (size_t)kk * 4096);
                float4* dst = (float4*)B[nb];
                for (int t = ptid; t < 1024; t += 128) dst[t] = src[t];
            }
            PBAR();
            // 4) gather
            int m = nv[nb];
            if (nb == 0) mprev0 = m; else mprev1 = m;
            for (int t = ptid; t < m * 16; t += 128) {
                int e = t >> 4, pc = t & 15;
                int u = vl[e];
                int v = u >> 17, n = u & 0x1FFFF;
                float4 fv = ((const float4*)feats)[(size_t)n * 16 + pc];
                float4 o;
                o.x = __uint_as_float(f2tf32(fv.x));
                o.y = __uint_as_float(f2tf32(fv.y));
                o.z = __uint_as_float(f2tf32(fv.z));
                o.w = __uint_as_float(f2tf32(fv.w));
                *(float4*)(Ab + v * ASTR + pc * 4) = o;
            }
        }
        __syncthreads();
    }

    // ---- epilogue: bias, store g_x, GN partials ----
    float s0 = 0.f, s1 = 0.f, q0 = 0.f, q1 = 0.f, c0 = 0.f, c1 = 0.f;
    if (isMMA) {
        #pragma unroll
        for (int s = 0; s < 4; s++) {
            const int lr0 = w * 64 + s * 16 + (lane >> 2);
            const int lr1 = lr0 + 8;
            const int b0i = bs[lr0], b1i = bs[lr1];
            const int gi0 = i0 + lr0, gi1 = i0 + lr1;
            #pragma unroll
            for (int n = 0; n < 8; n++) {
                const int col = n * 8 + (lane & 3) * 2;
                const float bb0 = __ldg(b_dw + col);
                const float bb1 = __ldg(b_dw + col + 1);
                if (b0i >= 0) {
                    float x0 = acc[s][n][0] + bb0;
                    float x1 = acc[s][n][1] + bb1;
                    *(float2*)(g_x + (size_t)gi0 * CDIM + col) = make_float2(x0, x1);
                    if (b0i == 0) { s0 += x0 + x1; q0 += x0 * x0 + x1 * x1; }
                    else          { s1 += x0 + x1; q1 += x0 * x0 + x1 * x1; }
                }
                if (b1i >= 0) {
                    float x2 = acc[s][n][2] + bb0;
                    float x3 = acc[s][n][3] + bb1;
                    *(float2*)(g_x + (size_t)gi1 * CDIM + col) = make_float2(x2, x3);
                    if (b1i == 0) { s0 += x2 + x3; q0 += x2 * x2 + x3 * x3; }
                    else          { s1 += x2 + x3; q1 += x2 * x2 + x3 * x3; }
                }
            }
            if ((lane & 3) == 0) {
                if (b0i == 0) c0 += 1.f; else if (b0i == 1) c1 += 1.f;
                if (b1i == 0) c0 += 1.f; else if (b1i == 1) c1 += 1.f;
            }
        }
    }
    __syncthreads();
    float* red = A[0];
    red[0 * NT + tid] = s0;
    red[1 * NT + tid] = s1;
    red[2 * NT + tid] = q0;
    red[3 * NT + tid] = q1;
    red[4 * NT + tid] = c0;
    red[5 * NT + tid] = c1;
    __syncthreads();
    for (int off = NT / 2; off > 0; off >>= 1) {
        if (tid < off) {
            #pragma unroll
            for (int a = 0; a < 6; a++) red[a * NT + tid] += red[a * NT + tid + off];
        }
        __syncthreads();
    }
    if (tid == 0) {
        float* pp = g_part1 + blockIdx.x * 8;
        #pragma unroll
        for (int a = 0; a < 6; a++) pp[a] = red[a * NT];
    }
}

// ================= GN finalize (parallel) =================
__global__ void __launch_bounds__(NT) gn_finalize() {
    __shared__ float red[8][32];
    const int t = threadIdx.x;
    const int comp = t & 7, stripe = t >> 3;
    float s = 0.f;
    if (comp < 6)
        for (int b = stripe; b < CBLK; b += 32) s += g_part1[b * 8 + comp];
    red[comp][stripe] = s;
    __syncthreads();
    if (t < 8) {
        float a = 0.f;
        #pragma unroll
        for (int i = 0; i < 32; i++) a += red[t][i];
        red[t][0] = a;
    }
    __syncthreads();
    if (t == 0) {
        double cnt0 = (double)red[4][0] * CDIM, cnt1 = (double)red[5][0] * CDIM;
        double m0 = (double)red[0][0] / cnt0, m1 = (double)red[1][0] / cnt1;
        double v0 = (double)red[2][0] / cnt0 - m0 * m0;
        double v1 = (double)red[3][0] / cnt1 - m1 * m1;
        g_gn[0] = (float)m0;
        g_gn[1] = (float)(1.0 / sqrt(v0 + 1e-6));
        g_gn[2] = (float)m1;
        g_gn[3] = (float)(1.0 / sqrt(v1 + 1e-6));
    }
}

// ================= pw1: GN apply + x@w_pw1 + ReLU + y^2 partials =================
__global__ void __launch_bounds__(NT) pw1_kernel(
    const float* __restrict__ w_pw1,
    const float* __restrict__ gn_gamma,
    const float* __restrict__ gn_beta,
    const int*   __restrict__ batch_ids)
{
    extern __shared__ __align__(16) unsigned char smraw[];
    float* ws1 = (float*)smraw;
    float* xs  = ws1 + CDIM * C4;
    int*   bs  = (int*)(xs + PTILE * CDIM);

    const int tid = threadIdx.x;
    const int i0 = blockIdx.x * PTILE;
    const int rows = min(PTILE, NVOX - i0);
    const int j = tid;

    for (int t = tid; t < CDIM * C4; t += NT) ws1[t] = w_pw1[t];
    if (tid < PTILE) {
        int gi = i0 + tid;
        bs[tid] = (gi < NVOX) ? batch_ids[gi] : 0;
    }
    __syncthreads();
    const float mean0 = g_gn[0], rinv0 = g_gn[1], mean1 = g_gn[2], rinv1 = g_gn[3];
    for (int t = tid; t < PTILE * CDIM; t += NT) {
        int v = t >> 6, cc = t & 63;
        float xv = 0.f;
        if (v < rows) {
            int b = bs[v];
            float x = g_x[(size_t)(i0 + v) * CDIM + cc];
            float mn = (b == 0) ? mean0 : mean1;
            float ri = (b == 0) ? rinv0 : rinv1;
            xv = (x - mn) * ri * gn_gamma[cc] + gn_beta[cc];
        }
        xs[t] = xv;
    }
    __syncthreads();

    float pb0 = 0.f, pb1 = 0.f;
    for (int v0 = 0; v0 < PTILE; v0 += 8) {
        float s[8];
        #pragma unroll
        for (int r = 0; r < 8; r++) s[r] = 0.f;
        for (int cc = 0; cc < CDIM; cc += 4) {
            float w0 = ws1[(cc + 0) * C4 + j];
            float w1 = ws1[(cc + 1) * C4 + j];
            float w2 = ws1[(cc + 2) * C4 + j];
            float w3 = ws1[(cc + 3) * C4 + j];
            #pragma unroll
            for (int r = 0; r < 8; r++) {
                float4 a = *(const float4*)&xs[(v0 + r) * CDIM + cc];
                s[r] += a.x * w0 + a.y * w1 + a.z * w2 + a.w * w3;
            }
        }
        #pragma unroll
        for (int r = 0; r < 8; r++) {
            int v = v0 + r;
            if (v < rows) {
                float y = fmaxf(s[r], 0.f);
                g_y[(size_t)(i0 + v) * C4 + j] = y;
                if (bs[v] == 0) pb0 += y * y; else pb1 += y * y;
            }
        }
    }
    g_part2[blockIdx.x * (2 * C4) + j]      = pb0;
    g_part2[blockIdx.x * (2 * C4) + C4 + j] = pb1;
}

// ================= GRN stage1 + finalize =================
__global__ void __launch_bounds__(128) grn_stage1() {
    __shared__ float red[128];
    const int s = blockIdx.x;
    float a = 0.f;
    for (int b = threadIdx.x; b < PBLK; b += 128) a += g_part2[b * 512 + s];
    red[threadIdx.x] = a;
    __syncthreads();
    for (int off = 64; off > 0; off >>= 1) {
        if (threadIdx.x < off) red[threadIdx.x] += red[threadIdx.x + off];
        __syncthreads();
    }
    if (threadIdx.x == 0) g_gx2[s] = red[0];
}

__global__ void __launch_bounds__(C4) grn_finalize(
    const float* __restrict__ grn_gamma,
    const float* __restrict__ grn_beta,
    const float* __restrict__ w_pw2)
{
    __shared__ float r0[C4], r1[C4], bt[4][CDIM];
    const int j = threadIdx.x;
    float gx0 = sqrtf(g_gx2[j]);
    float gx1 = sqrtf(g_gx2[C4 + j]);
    r0[j] = gx0; r1[j] = gx1;
    __syncthreads();
    for (int off = C4 / 2; off > 0; off >>= 1) {
        if (j < off) { r0[j] += r0[j + off]; r1[j] += r1[j + off]; }
        __syncthreads();
    }
    float m0 = r0[0] / (float)C4;
    float m1 = r1[0] / (float)C4;
    float gam = grn_gamma[j];
    g_sj[j]      = 1.f + gam * (gx0 / (m0 + 1e-6f));
    g_sj[C4 + j] = 1.f + gam * (gx1 / (m1 + 1e-6f));
    const int part = j >> 6, jc = j & 63;
    float s = 0.f;
    for (int jj = part * 64; jj < part * 64 + 64; jj++)
        s += grn_beta[jj] * w_pw2[jj * CDIM + jc];
    bt[part][jc] = s;
    __syncthreads();
    if (j < CDIM) g_bterm[j] = bt[0][j] + bt[1][j] + bt[2][j] + bt[3][j];
}

// ================= pw2 =================
__global__ void __launch_bounds__(NT) pw2_kernel(
    const float* __restrict__ feats,
    const float* __restrict__ w_pw2,
    const int*   __restrict__ batch_ids,
    float* __restrict__ out)
{
    extern __shared__ __align__(16) unsigned char smraw[];
    float* ys  = (float*)smraw;
    float* w2s = ys + PTILE * CDIM;
    float* ssm = w2s + CDIM * CDIM;
    int*   bs  = (int*)(ssm + 2 * C4);

    const int tid = threadIdx.x;
    const int i0 = blockIdx.x * PTILE;
    const int rows = min(PTILE, NVOX - i0);
    const int c = tid & 63;
    const int g = tid >> 6;

    for (int t = tid; t < 2 * C4; t += NT) ssm[t] = g_sj[t];
    if (tid < PTILE) {
        int gi = i0 + tid;
        bs[tid] = (gi < NVOX) ? batch_ids[gi] : 0;
    }

    float accr[32];
    #pragma unroll
    for (int r = 0; r < 32; r++) accr[r] = 0.f;

    for (int jc = 0; jc < 4; jc++) {
        __syncthreads();
        for (int t = tid; t < CDIM * CDIM; t += NT)
            w2s[t] = w_pw2[(jc * CDIM + (t >> 6)) * CDIM + (t & 63)];
        for (int t = tid; t < PTILE * CDIM; t += NT) {
            int v = t >> 6, jj = t & 63;
            float y = 0.f;
            if (v < rows)
                y = g_y[(size_t)(i0 + v) * C4 + jc * CDIM + jj]
                    * ssm[bs[v] * C4 + jc * CDIM + jj];
            ys[t] = y;
        }
        __syncthreads();
        #pragma unroll
        for (int r = 0; r < 32; r += 2) {
            const float* y0 = ys + (g + 4 * r) * CDIM;
            const float* y1 = ys + (g + 4 * r + 4) * CDIM;
            float sA = accr[r], sB = accr[r + 1];
            #pragma unroll
            for (int jj = 0; jj < CDIM; jj += 4) {
                float w0 = w2s[(jj + 0) * CDIM + c];
                float w1 = w2s[(jj + 1) * CDIM + c];
                float w2 = w2s[(jj + 2) * CDIM + c];
                float w3 = w2s[(jj + 3) * CDIM + c];
                float4 a0 = *(const float4*)(y0 + jj);
                float4 a1 = *(const float4*)(y1 + jj);
                sA += a0.x * w0 + a0.y * w1 + a0.z * w2 + a0.w * w3;
                sB += a1.x * w0 + a1.y * w1 + a1.z * w2 + a1.w * w3;
            }
            accr[r] = sA; accr[r + 1] = sB;
        }
    }
    const float btv = g_bterm[c];
    #pragma unroll
    for (int r = 0; r < 32; r++) {
        int v = g + 4 * r;
        int gi = i0 + v;
        if (v < rows)
            out[(size_t)gi * CDIM + c] = feats[(size_t)gi * CDIM + c] + accr[r] + btv;
    }
}

// ================= launch =================
#define PW1_SMEM 99328
#define PW2_SMEM 52224

extern "C" void kernel_launch(void* const* d_in, const int* in_sizes, int n_in,
                              void* d_out, int out_size)
{
    const float* feats     = (const float*)d_in[0];
    const float* w_dw      = (const float*)d_in[1];
    const float* b_dw      = (const float*)d_in[2];
    const float* gn_gamma  = (const float*)d_in[3];
    const float* gn_beta   = (const float*)d_in[4];
    const float* w_pw1     = (const float*)d_in[5];
    const float* grn_gamma = (const float*)d_in[6];
    const float* grn_beta  = (const float*)d_in[7];
    const float* w_pw2     = (const float*)d_in[8];
    const int*   nbr       = (const int*)d_in[9];
    const int*   batch_ids = (const int*)d_in[10];
    float* out = (float*)d_out;

    cudaFuncSetAttribute(conv_kernel, cudaFuncAttributeMaxDynamicSharedMemorySize, CONV_SMEM);
    cudaFuncSetAttribute(pw1_kernel,  cudaFuncAttributeMaxDynamicSharedMemorySize, PW1_SMEM);
    cudaFuncSetAttribute(pw2_kernel,  cudaFuncAttributeMaxDynamicSharedMemorySize, PW2_SMEM);

    prep_wB<<<KKTOT, NT>>>(w_dw);
    conv_kernel<<<CBLK, NT, CONV_SMEM>>>(feats, b_dw, nbr, batch_ids);
    gn_finalize<<<1, NT>>>();
    pw1_kernel<<<PBLK, NT, PW1_SMEM>>>(w_pw1, gn_gamma, gn_beta, batch_ids);
    grn_stage1<<<512, 128>>>();
    grn_finalize<<<1, C4>>>(grn_gamma, grn_beta, w_pw2);
    pw2_kernel<<<PBLK, NT, PW2_SMEM>>>(feats, w_pw2, batch_ids, out);
}

// round 5
// speedup vs baseline: 1.2772x; 1.2772x over previous
#include <cuda_runtime.h>
#include <cstdint>
#include <math.h>

#define NVOX 100000
#define CDIM 64
#define C4   256
#define KKTOT 343
#define TILE 128          // voxels per conv CTA
#define NT   256
#define CBLK 782          // ceil(NVOX/TILE)
#define PTILE 128
#define PBLK 782
#define ASTR 68           // A smem row stride (floats), conflict-free frag loads
#define AROWS 64          // compacted A capacity (m>64 is ~9-sigma; fallback exists)

// ---------------- static scratch ----------------
__device__ float g_x[(size_t)NVOX * CDIM];
__device__ float g_y[(size_t)NVOX * C4];
__device__ float g_wB[(size_t)KKTOT * CDIM * CDIM];   // B tiles in mma-fragment layout, tf32-rounded
__device__ float g_part1[CBLK * 8];
__device__ float g_part2[PBLK * 2 * C4];
__device__ float g_gx2[2 * C4];
__device__ float g_gn[4];
__device__ float g_sj[2 * C4];
__device__ float g_bterm[CDIM];

// ---------------- smem layout (bytes) ----------------
#define OFF_ACC  0                         // 128*65*4 = 33280
#define OFF_A0   33280                     // 64*68*4 = 17408
#define OFF_A1   50688
#define OFF_B0   68096                     // 16384
#define OFF_B1   84480
#define OFF_SIDX 100864                    // 128*7*4 = 3584
#define OFF_VL0  104448                    // 512
#define OFF_VL1  104960
#define OFF_BS   105472                    // 512
#define OFF_NV   105984                    // 8
#define CONV_SMEM 106496

__device__ __forceinline__ uint32_t f2tf32(float x) {
    uint32_t r;
    asm("cvt.rna.tf32.f32 %0, %1;" : "=r"(r) : "f"(x));
    return r;
}

__device__ __forceinline__ void mma_tf32(float c[4], uint32_t a0, uint32_t a1,
                                         uint32_t a2, uint32_t a3,
                                         uint32_t b0, uint32_t b1) {
    asm volatile(
        "mma.sync.aligned.m16n8k8.row.col.f32.tf32.tf32.f32 "
        "{%0,%1,%2,%3}, {%4,%5,%6,%7}, {%8,%9}, {%0,%1,%2,%3};"
        : "+f"(c[0]), "+f"(c[1]), "+f"(c[2]), "+f"(c[3])
        : "r"(a0), "r"(a1), "r"(a2), "r"(a3), "r"(b0), "r"(b1));
}

#define PBAR() asm volatile("bar.sync 1, 128;" ::: "memory")

// ================= prep: w_dw[k] -> B-fragment layout, tf32-rounded =================
__global__ void __launch_bounds__(NT) prep_wB(const float* __restrict__ w_dw) {
    const int k = blockIdx.x;
    const float* wk = w_dw + (size_t)k * 4096;
    float* dst = g_wB + (size_t)k * 4096;
    for (int t = threadIdx.x; t < 4096; t += NT) {
        int cin = t >> 6, cout = t & 63;
        int kstep = cin >> 3, kk = cin & 7;
        int nt = cout >> 3, nn = cout & 7;
        int idx = (((kstep * 8 + nt) * 32 + nn * 4 + (kk & 3)) << 1) + (kk >> 2);
        dst[idx] = __uint_as_float(f2tf32(wk[t]));
    }
}

// ================= conv: M-compacted warp-specialized tf32 mma.sync =================
__global__ void __launch_bounds__(NT, 2) conv_kernel(
    const float* __restrict__ feats,
    const float* __restrict__ w_dw,
    const float* __restrict__ b_dw,
    const int*   __restrict__ nbr,
    const int*   __restrict__ batch_ids)
{
    extern __shared__ __align__(16) unsigned char smraw[];
    float* acc   = (float*)(smraw + OFF_ACC);
    float* A[2]  = { (float*)(smraw + OFF_A0), (float*)(smraw + OFF_A1) };
    float* B[2]  = { (float*)(smraw + OFF_B0), (float*)(smraw + OFF_B1) };
    int* sidx    = (int*)(smraw + OFF_SIDX);
    int* VL[2]   = { (int*)(smraw + OFF_VL0), (int*)(smraw + OFF_VL1) };
    int* bs      = (int*)(smraw + OFF_BS);
    int* nv      = (int*)(smraw + OFF_NV);

    const int tid  = threadIdx.x;
    const int lane = tid & 31;
    const int i0   = blockIdx.x * TILE;
    const bool isMMA = tid < 128;
    const int w    = tid >> 5;           // mma warps 0..3 (n-quarter owner)
    const int ptid = tid - 128;          // producers 0..127

    // zero acc
    {
        float4 z = make_float4(0.f, 0.f, 0.f, 0.f);
        for (int t = tid; t < TILE * 65 / 4 - 1; t += NT) ((float4*)acc)[t] = z;
        if (tid == 0) { acc[TILE * 65 - 4] = 0.f; acc[TILE * 65 - 3] = 0.f;
                        acc[TILE * 65 - 2] = 0.f; acc[TILE * 65 - 1] = 0.f; }
    }
    if (tid < TILE) {
        int gi = i0 + tid;
        bs[tid] = (gi < NVOX) ? batch_ids[gi] : -1;
    }
    if (tid == 0) { nv[0] = 0; nv[1] = 0; }
    __syncthreads();

    // ---- prologue: produce buffer 0 for k=0 ----
    if (!isMMA) {
        for (int t = ptid; t < TILE * 7; t += 128) {
            int r = t / 7, j = t - r * 7;
            int gi = i0 + r;
            sidx[t] = (gi < NVOX) ? nbr[(long long)gi * KKTOT + j] : NVOX;
        }
        PBAR();
        {
            int r = ptid;
            int n = sidx[r * 7];
            if (n < NVOX) {
                int slot = atomicAdd(&nv[0], 1);
                VL[0][slot] = (r << 17) | n;
            }
        }
        {
            const float4* src = (const float4*)(g_wB);
            float4* dst = (float4*)B[0];
            for (int t = ptid; t < 1024; t += 128) dst[t] = src[t];
        }
        PBAR();
        int m = min(nv[0], AROWS);
        for (int t = ptid; t < m * 16; t += 128) {
            int e = t >> 4, pc = t & 15;
            int n = VL[0][e] & 0x1FFFF;
            float4 fv = ((const float4*)feats)[(size_t)n * 16 + pc];
            float4 o;
            o.x = __uint_as_float(f2tf32(fv.x));
            o.y = __uint_as_float(f2tf32(fv.y));
            o.z = __uint_as_float(f2tf32(fv.z));
            o.w = __uint_as_float(f2tf32(fv.w));
            *(float4*)(A[0] + e * ASTR + pc * 4) = o;
        }
    }
    __syncthreads();

    // ---- main loop ----
    for (int k = 0; k < KKTOT; k++) {
        const int buf = k & 1;
        if (isMMA) {
            const int m = nv[buf];
            const int mcap = min(m, AROWS);
            const int mtiles = (mcap + 15) >> 4;
            if (mtiles > 0) {
                const float2* Bf = (const float2*)B[buf];
                float2 bv0[8], bv1[8];
                #pragma unroll
                for (int ks = 0; ks < 8; ks++) {
                    bv0[ks] = Bf[(ks * 8 + 2 * w) * 32 + lane];
                    bv1[ks] = Bf[(ks * 8 + 2 * w + 1) * 32 + lane];
                }
                const int* vl = VL[buf];
                const float* Ab = A[buf];
                const int r0 = lane >> 2, cq = lane & 3;
                const int cb0 = w * 16 + cq * 2;
                for (int mt = 0; mt < mtiles; mt++) {
                    float c0[4] = {0.f, 0.f, 0.f, 0.f};
                    float c1[4] = {0.f, 0.f, 0.f, 0.f};
                    const float* Ap = Ab + (mt * 16 + r0) * ASTR + cq;
                    #pragma unroll
                    for (int ks = 0; ks < 8; ks++) {
                        uint32_t a0 = __float_as_uint(Ap[ks * 8]);
                        uint32_t a1 = __float_as_uint(Ap[8 * ASTR + ks * 8]);
                        uint32_t a2 = __float_as_uint(Ap[ks * 8 + 4]);
                        uint32_t a3 = __float_as_uint(Ap[8 * ASTR + ks * 8 + 4]);
                        mma_tf32(c0, a0, a1, a2, a3,
                                 __float_as_uint(bv0[ks].x), __float_as_uint(bv0[ks].y));
                        mma_tf32(c1, a0, a1, a2, a3,
                                 __float_as_uint(bv1[ks].x), __float_as_uint(bv1[ks].y));
                    }
                    const int e0 = mt * 16 + r0, e1 = e0 + 8;
                    if (e0 < mcap) {
                        float* a = acc + (vl[e0] >> 17) * 65 + cb0;
                        a[0] += c0[0]; a[1] += c0[1];
                        a[8] += c1[0]; a[9] += c1[1];
                    }
                    if (e1 < mcap) {
                        float* a = acc + (vl[e1] >> 17) * 65 + cb0;
                        a[0] += c0[2]; a[1] += c0[3];
                        a[8] += c1[2]; a[9] += c1[3];
                    }
                }
                if (m > AROWS) {   // statistically unreachable fallback (kept for correctness)
                    for (int t = tid; t < (m - AROWS) * 64; t += 128) {
                        int e = AROWS + (t >> 6), c = t & 63;
                        int u = vl[e];
                        int vv = u >> 17, n = u & 0x1FFFF;
                        const float* fr = feats + (size_t)n * 64;
                        const float* wr = w_dw + (size_t)k * 4096 + c;
                        float s = 0.f;
                        for (int ci = 0; ci < 64; ci++) s += fr[ci] * wr[ci * 64];
                        acc[vv * 65 + c] += s;
                    }
                }
            }
        } else if (k + 1 < KKTOT) {
            const int kk = k + 1;
            const int nb = buf ^ 1;
            int* vl = VL[nb];
            float* Ab = A[nb];
            if ((kk % 7) == 0) {
                for (int t = ptid; t < TILE * 7; t += 128) {
                    int r = t / 7, j = t - r * 7;
                    int gi = i0 + r;
                    sidx[t] = (gi < NVOX) ? nbr[(long long)gi * KKTOT + kk + j] : NVOX;
                }
            }
            if (ptid == 0) nv[nb] = 0;
            PBAR();
            {
                int r = ptid;
                int n = sidx[r * 7 + (kk % 7)];
                if (n < NVOX) {
                    int slot = atomicAdd(&nv[nb], 1);
                    vl[slot] = (r << 17) | n;
                }
            }
            {
                const float4* src = (const float4*)(g_wB + (size_t)kk * 4096);
                float4* dst = (float4*)B[nb];
                for (int t = ptid; t < 1024; t += 128) dst[t] = src[t];
            }
            PBAR();
            int m = min(nv[nb], AROWS);
            for (int t = ptid; t < m * 16; t += 128) {
                int e = t >> 4, pc = t & 15;
                int n = vl[e] & 0x1FFFF;
                float4 fv = ((const float4*)feats)[(size_t)n * 16 + pc];
                float4 o;
                o.x = __uint_as_float(f2tf32(fv.x));
                o.y = __uint_as_float(f2tf32(fv.y));
                o.z = __uint_as_float(f2tf32(fv.z));
                o.w = __uint_as_float(f2tf32(fv.w));
                *(float4*)(Ab + e * ASTR + pc * 4) = o;
            }
        }
        __syncthreads();
    }

    // ---- epilogue: bias, store g_x, GN partials ----
    const int v = tid >> 1;
    const int ch = (tid & 1) * 32;
    const int gi = i0 + v;
    const int b = bs[v];
    float s = 0.f, q = 0.f, cnt = 0.f;
    if (gi < NVOX) {
        float* dst = g_x + (size_t)gi * CDIM + ch;
        const float* ar = acc + v * 65 + ch;
        #pragma unroll
        for (int c = 0; c < 32; c += 4) {
            float x0 = ar[c + 0] + b_dw[ch + c + 0];
            float x1 = ar[c + 1] + b_dw[ch + c + 1];
            float x2 = ar[c + 2] + b_dw[ch + c + 2];
            float x3 = ar[c + 3] + b_dw[ch + c + 3];
            *(float4*)(dst + c) = make_float4(x0, x1, x2, x3);
            s += x0 + x1 + x2 + x3;
            q += x0 * x0 + x1 * x1 + x2 * x2 + x3 * x3;
        }
        if ((tid & 1) == 0) cnt = 1.f;
    }
    __syncthreads();   // all acc reads done before reusing as reduction space
    float* red = (float*)smraw;
    red[0 * NT + tid] = (b == 0) ? s : 0.f;
    red[1 * NT + tid] = (b == 1) ? s : 0.f;
    red[2 * NT + tid] = (b == 0) ? q : 0.f;
    red[3 * NT + tid] = (b == 1) ? q : 0.f;
    red[4 * NT + tid] = (b == 0) ? cnt : 0.f;
    red[5 * NT + tid] = (b == 1) ? cnt : 0.f;
    __syncthreads();
    for (int off = NT / 2; off > 0; off >>= 1) {
        if (tid < off) {
            #pragma unroll
            for (int a = 0; a < 6; a++) red[a * NT + tid] += red[a * NT + tid + off];
        }
        __syncthreads();
    }
    if (tid == 0) {
        float* pp = g_part1 + blockIdx.x * 8;
        #pragma unroll
        for (int a = 0; a < 6; a++) pp[a] = red[a * NT];
    }
}

// ================= GN finalize (parallel) =================
__global__ void __launch_bounds__(NT) gn_finalize() {
    __shared__ float red[8][32];
    const int t = threadIdx.x;
    const int comp = t & 7, stripe = t >> 3;
    float s = 0.f;
    if (comp < 6)
        for (int b = stripe; b < CBLK; b += 32) s += g_part1[b * 8 + comp];
    red[comp][stripe] = s;
    __syncthreads();
    if (t < 8) {
        float a = 0.f;
        #pragma unroll
        for (int i = 0; i < 32; i++) a += red[t][i];
        red[t][0] = a;
    }
    __syncthreads();
    if (t == 0) {
        double cnt0 = (double)red[4][0] * CDIM, cnt1 = (double)red[5][0] * CDIM;
        double m0 = (double)red[0][0] / cnt0, m1 = (double)red[1][0] / cnt1;
        double v0 = (double)red[2][0] / cnt0 - m0 * m0;
        double v1 = (double)red[3][0] / cnt1 - m1 * m1;
        g_gn[0] = (float)m0;
        g_gn[1] = (float)(1.0 / sqrt(v0 + 1e-6));
        g_gn[2] = (float)m1;
        g_gn[3] = (float)(1.0 / sqrt(v1 + 1e-6));
    }
}

// ================= pw1 =================
__global__ void __launch_bounds__(NT) pw1_kernel(
    const float* __restrict__ w_pw1,
    const float* __restrict__ gn_gamma,
    const float* __restrict__ gn_beta,
    const int*   __restrict__ batch_ids)
{
    extern __shared__ __align__(16) unsigned char smraw[];
    float* ws1 = (float*)smraw;
    float* xs  = ws1 + CDIM * C4;
    int*   bs  = (int*)(xs + PTILE * CDIM);

    const int tid = threadIdx.x;
    const int i0 = blockIdx.x * PTILE;
    const int rows = min(PTILE, NVOX - i0);
    const int j = tid;

    for (int t = tid; t < CDIM * C4; t += NT) ws1[t] = w_pw1[t];
    if (tid < PTILE) {
        int gi = i0 + tid;
        bs[tid] = (gi < NVOX) ? batch_ids[gi] : 0;
    }
    __syncthreads();
    const float mean0 = g_gn[0], rinv0 = g_gn[1], mean1 = g_gn[2], rinv1 = g_gn[3];
    for (int t = tid; t < PTILE * CDIM; t += NT) {
        int v = t >> 6, cc = t & 63;
        float xv = 0.f;
        if (v < rows) {
            int b = bs[v];
            float x = g_x[(size_t)(i0 + v) * CDIM + cc];
            float mn = (b == 0) ? mean0 : mean1;
            float ri = (b == 0) ? rinv0 : rinv1;
            xv = (x - mn) * ri * gn_gamma[cc] + gn_beta[cc];
        }
        xs[t] = xv;
    }
    __syncthreads();

    float pb0 = 0.f, pb1 = 0.f;
    for (int v0 = 0; v0 < PTILE; v0 += 8) {
        float s[8];
        #pragma unroll
        for (int r = 0; r < 8; r++) s[r] = 0.f;
        for (int cc = 0; cc < CDIM; cc += 4) {
            float w0 = ws1[(cc + 0) * C4 + j];
            float w1 = ws1[(cc + 1) * C4 + j];
            float w2 = ws1[(cc + 2) * C4 + j];
            float w3 = ws1[(cc + 3) * C4 + j];
            #pragma unroll
            for (int r = 0; r < 8; r++) {
                float4 a = *(const float4*)&xs[(v0 + r) * CDIM + cc];
                s[r] += a.x * w0 + a.y * w1 + a.z * w2 + a.w * w3;
            }
        }
        #pragma unroll
        for (int r = 0; r < 8; r++) {
            int v = v0 + r;
            if (v < rows) {
                float y = fmaxf(s[r], 0.f);
                g_y[(size_t)(i0 + v) * C4 + j] = y;
                if (bs[v] == 0) pb0 += y * y; else pb1 += y * y;
            }
        }
    }
    g_part2[blockIdx.x * (2 * C4) + j]      = pb0;
    g_part2[blockIdx.x * (2 * C4) + C4 + j] = pb1;
}

// ================= GRN stage1 + finalize =================
__global__ void __launch_bounds__(128) grn_stage1() {
    __shared__ float red[128];
    const int s = blockIdx.x;
    float a = 0.f;
    for (int b = threadIdx.x; b < PBLK; b += 128) a += g_part2[b * 512 + s];
    red[threadIdx.x] = a;
    __syncthreads();
    for (int off = 64; off > 0; off >>= 1) {
        if (threadIdx.x < off) red[threadIdx.x] += red[threadIdx.x + off];
        __syncthreads();
    }
    if (threadIdx.x == 0) g_gx2[s] = red[0];
}

__global__ void __launch_bounds__(C4) grn_finalize(
    const float* __restrict__ grn_gamma,
    const float* __restrict__ grn_beta,
    const float* __restrict__ w_pw2)
{
    __shared__ float r0[C4], r1[C4], bt[4][CDIM];
    const int j = threadIdx.x;
    float gx0 = sqrtf(g_gx2[j]);
    float gx1 = sqrtf(g_gx2[C4 + j]);
    r0[j] = gx0; r1[j] = gx1;
    __syncthreads();
    for (int off = C4 / 2; off > 0; off >>= 1) {
        if (j < off) { r0[j] += r0[j + off]; r1[j] += r1[j + off]; }
        __syncthreads();
    }
    float m0 = r0[0] / (float)C4;
    float m1 = r1[0] / (float)C4;
    float gam = grn_gamma[j];
    g_sj[j]      = 1.f + gam * (gx0 / (m0 + 1e-6f));
    g_sj[C4 + j] = 1.f + gam * (gx1 / (m1 + 1e-6f));
    const int part = j >> 6, jc = j & 63;
    float s = 0.f;
    for (int jj = part * 64; jj < part * 64 + 64; jj++)
        s += grn_beta[jj] * w_pw2[jj * CDIM + jc];
    bt[part][jc] = s;
    __syncthreads();
    if (j < CDIM) g_bterm[j] = bt[0][j] + bt[1][j] + bt[2][j] + bt[3][j];
}

// ================= pw2 =================
__global__ void __launch_bounds__(NT) pw2_kernel(
    const float* __restrict__ feats,
    const float* __restrict__ w_pw2,
    const int*   __restrict__ batch_ids,
    float* __restrict__ out)
{
    extern __shared__ __align__(16) unsigned char smraw[];
    float* ys  = (float*)smraw;
    float* w2s = ys + PTILE * CDIM;
    float* ssm = w2s + CDIM * CDIM;
    int*   bs  = (int*)(ssm + 2 * C4);

    const int tid = threadIdx.x;
    const int i0 = blockIdx.x * PTILE;
    const int rows = min(PTILE, NVOX - i0);
    const int c = tid & 63;
    const int g = tid >> 6;

    for (int t = tid; t < 2 * C4; t += NT) ssm[t] = g_sj[t];
    if (tid < PTILE) {
        int gi = i0 + tid;
        bs[tid] = (gi < NVOX) ? batch_ids[gi] : 0;
    }

    float accr[32];
    #pragma unroll
    for (int r = 0; r < 32; r++) accr[r] = 0.f;

    for (int jc = 0; jc < 4; jc++) {
        __syncthreads();
        for (int t = tid; t < CDIM * CDIM; t += NT)
            w2s[t] = w_pw2[(jc * CDIM + (t >> 6)) * CDIM + (t & 63)];
        for (int t = tid; t < PTILE * CDIM; t += NT) {
            int v = t >> 6, jj = t & 63;
            float y = 0.f;
            if (v < rows)
                y = g_y[(size_t)(i0 + v) * C4 + jc * CDIM + jj]
                    * ssm[bs[v] * C4 + jc * CDIM + jj];
            ys[t] = y;
        }
        __syncthreads();
        #pragma unroll
        for (int r = 0; r < 32; r += 2) {
            const float* y0 = ys + (g + 4 * r) * CDIM;
            const float* y1 = ys + (g + 4 * r + 4) * CDIM;
            float sA = accr[r], sB = accr[r + 1];
            #pragma unroll
            for (int jj = 0; jj < CDIM; jj += 4) {
                float w0 = w2s[(jj + 0) * CDIM + c];
                float w1 = w2s[(jj + 1) * CDIM + c];
                float w2 = w2s[(jj + 2) * CDIM + c];
                float w3 = w2s[(jj + 3) * CDIM + c];
                float4 a0 = *(const float4*)(y0 + jj);
                float4 a1 = *(const float4*)(y1 + jj);
                sA += a0.x * w0 + a0.y * w1 + a0.z * w2 + a0.w * w3;
                sB += a1.x * w0 + a1.y * w1 + a1.z * w2 + a1.w * w3;
            }
            accr[r] = sA; accr[r + 1] = sB;
        }
    }
    const float btv = g_bterm[c];
    #pragma unroll
    for (int r = 0; r < 32; r++) {
        int v = g + 4 * r;
        int gi = i0 + v;
        if (v < rows)
            out[(size_t)gi * CDIM + c] = feats[(size_t)gi * CDIM + c] + accr[r] + btv;
    }
}

// ================= launch =================
#define PW1_SMEM 99328
#define PW2_SMEM 52224

extern "C" void kernel_launch(void* const* d_in, const int* in_sizes, int n_in,
                              void* d_out, int out_size)
{
    const float* feats     = (const float*)d_in[0];
    const float* w_dw      = (const float*)d_in[1];
    const float* b_dw      = (const float*)d_in[2];
    const float* gn_gamma  = (const float*)d_in[3];
    const float* gn_beta   = (const float*)d_in[4];
    const float* w_pw1     = (const float*)d_in[5];
    const float* grn_gamma = (const float*)d_in[6];
    const float* grn_beta  = (const float*)d_in[7];
    const float* w_pw2     = (const float*)d_in[8];
    const int*   nbr       = (const int*)d_in[9];
    const int*   batch_ids = (const int*)d_in[10];
    float* out = (float*)d_out;

    cudaFuncSetAttribute(conv_kernel, cudaFuncAttributeMaxDynamicSharedMemorySize, CONV_SMEM);
    cudaFuncSetAttribute(pw1_kernel,  cudaFuncAttributeMaxDynamicSharedMemorySize, PW1_SMEM);
    cudaFuncSetAttribute(pw2_kernel,  cudaFuncAttributeMaxDynamicSharedMemorySize, PW2_SMEM);

    prep_wB<<<KKTOT, NT>>>(w_dw);
    conv_kernel<<<CBLK, NT, CONV_SMEM>>>(feats, w_dw, b_dw, nbr, batch_ids);
    gn_finalize<<<1, NT>>>();
    pw1_kernel<<<PBLK, NT, PW1_SMEM>>>(w_pw1, gn_gamma, gn_beta, batch_ids);
    grn_stage1<<<512, 128>>>();
    grn_finalize<<<1, C4>>>(grn_gamma, grn_beta, w_pw2);
    pw2_kernel<<<PBLK, NT, PW2_SMEM>>>(feats, w_pw2, batch_ids, out);
}

// round 6
// speedup vs baseline: 2.6734x; 2.0933x over previous
#include <cuda_runtime.h>
#include <cstdint>
#include <math.h>

#define NVOX 100000
#define CDIM 64
#define C4   256
#define KKTOT 343
#define TILE 256          // voxels per conv CTA
#define CNT  512          // conv threads
#define CBLK 391          // ceil(NVOX/256)
#define PTILE 128
#define PBLK 782
#define NT   256
#define ASTR 68
#define SEGCAP 68
#define OVCAP  16
#define VLW    84         // SEGCAP+OVCAP

// ---------------- static scratch ----------------
__device__ float g_x[(size_t)NVOX * CDIM];
__device__ float g_y[(size_t)NVOX * C4];
__device__ float g_wB[(size_t)KKTOT * CDIM * CDIM];   // B fragment layout, tf32-rounded
__device__ float g_part1[CBLK * 8];
__device__ float g_part2[PBLK * 2 * C4];
__device__ float g_gx2[2 * C4];
__device__ float g_gn[4];
__device__ float g_sj[2 * C4];
__device__ float g_bterm[CDIM];

// ---------------- smem layout (bytes) ----------------
#define OFF_ACC  0                          // 256*65*4 = 66560
#define OFF_A0   66560                      // 272*68*4 = 73984
#define OFF_A1   140544
#define OFF_SIDX 214528                     // 256*4*4 = 4096
#define OFF_VL   218624                     // 2*4*84*4 = 2688
#define OFF_NV   221312                     // 8*4 = 32
#define OFF_BS   221344                     // 1024
#define CONV_SMEM 222400

__device__ __forceinline__ uint32_t f2tf32(float x) {
    uint32_t r;
    asm("cvt.rna.tf32.f32 %0, %1;" : "=r"(r) : "f"(x));
    return r;
}
__device__ __forceinline__ float tff(float x) { return __uint_as_float(f2tf32(x)); }

__device__ __forceinline__ void mma_tf32(float c[4], uint32_t a0, uint32_t a1,
                                         uint32_t a2, uint32_t a3,
                                         uint32_t b0, uint32_t b1) {
    asm volatile(
        "mma.sync.aligned.m16n8k8.row.col.f32.tf32.tf32.f32 "
        "{%0,%1,%2,%3}, {%4,%5,%6,%7}, {%8,%9}, {%0,%1,%2,%3};"
        : "+f"(c[0]), "+f"(c[1]), "+f"(c[2]), "+f"(c[3])
        : "r"(a0), "r"(a1), "r"(a2), "r"(a3), "r"(b0), "r"(b1));
}

#define PBAR() asm volatile("bar.sync 1, 256;" ::: "memory")
#define MBAR() asm volatile("bar.sync 2, 256;" ::: "memory")

// ================= prep: w_dw[k] -> B-fragment layout, tf32-rounded =================
__global__ void __launch_bounds__(NT) prep_wB(const float* __restrict__ w_dw) {
    const int k = blockIdx.x;
    const float* wk = w_dw + (size_t)k * 4096;
    float* dst = g_wB + (size_t)k * 4096;
    for (int t = threadIdx.x; t < 4096; t += NT) {
        int cin = t >> 6, cout = t & 63;
        int kstep = cin >> 3, kk = cin & 7;
        int nt = cout >> 3, nn = cout & 7;
        int idx = (((kstep * 8 + nt) * 32 + nn * 4 + (kk & 3)) << 1) + (kk >> 2);
        dst[idx] = __uint_as_float(f2tf32(wk[t]));
    }
}

// ================= conv: phase-batched, warp-specialized tf32 mma =================
__global__ void __launch_bounds__(CNT, 1) conv_kernel(
    const float* __restrict__ feats,
    const float* __restrict__ w_dw,
    const float* __restrict__ b_dw,
    const int*   __restrict__ nbr,
    const int*   __restrict__ batch_ids)
{
    extern __shared__ __align__(16) unsigned char smraw[];
    float* acc  = (float*)(smraw + OFF_ACC);
    float* AB[2] = { (float*)(smraw + OFF_A0), (float*)(smraw + OFF_A1) };
    int* sidx   = (int*)(smraw + OFF_SIDX);
    int* vl     = (int*)(smraw + OFF_VL);      // [buf][j][84]
    int* nv     = (int*)(smraw + OFF_NV);      // [buf][j]
    int* bs     = (int*)(smraw + OFF_BS);

    const int tid  = threadIdx.x;
    const int lane = tid & 31;
    const int warp = tid >> 5;
    const int i0   = blockIdx.x * TILE;
    const int rows = min(TILE, NVOX - i0);
    const bool isMMA = warp < 8;
    const int klocal = (warp >> 1) & 3;
    const int nhalf  = warp & 1;
    const int ptid   = tid - 256;

    // init
    {
        float4 z = make_float4(0.f, 0.f, 0.f, 0.f);
        for (int t = tid; t < TILE * 65 / 4; t += CNT) ((float4*)acc)[t] = z;
    }
    if (tid < TILE) bs[tid] = (tid < rows) ? batch_ids[i0 + tid] : -1;
    if (tid < 8) nv[tid] = 0;
    __syncthreads();

    // prologue: producers fill buf0 with the tile's own rows (center k = self)
    if (!isMMA) {
        const float4* f4g = (const float4*)feats;
        for (int t = ptid; t < rows * 16; t += 256) {
            int v = t >> 4, pc = t & 15;
            float4 fv = f4g[(size_t)(i0 + v) * 16 + pc];
            float4 o = make_float4(tff(fv.x), tff(fv.y), tff(fv.z), tff(fv.w));
            *(float4*)(AB[0] + v * ASTR + pc * 4) = o;
        }
    }
    __syncthreads();

    // phases: q=0 center (buf0), q=1..86 groups of 4 ks (excluding 171)
    for (int q = 0; q <= 86; q++) {
        const int buf = q & 1;
        if (isMMA) {
            if (q == 0) {
                // center k=171: dense rows, v == row
                const float2* Bf = (const float2*)(g_wB + (size_t)171 * 4096);
                float2 b[4][8];
                #pragma unroll
                for (int qn = 0; qn < 4; qn++)
                    #pragma unroll
                    for (int ks = 0; ks < 8; ks++)
                        b[qn][ks] = Bf[(ks * 8 + nhalf * 4 + qn) * 32 + lane];
                const float* Ab = AB[0];
                const int r0 = lane >> 2, cq = lane & 3;
                #pragma unroll
                for (int mi = 0; mi < 4; mi++) {
                    const int mt = (warp >> 1) + mi * 4;
                    float c[4][4];
                    #pragma unroll
                    for (int qn = 0; qn < 4; qn++)
                        #pragma unroll
                        for (int u = 0; u < 4; u++) c[qn][u] = 0.f;
                    const float* Ap = Ab + (mt * 16 + r0) * ASTR + cq;
                    #pragma unroll
                    for (int ks = 0; ks < 8; ks++) {
                        uint32_t a0 = __float_as_uint(Ap[ks * 8]);
                        uint32_t a1 = __float_as_uint(Ap[8 * ASTR + ks * 8]);
                        uint32_t a2 = __float_as_uint(Ap[ks * 8 + 4]);
                        uint32_t a3 = __float_as_uint(Ap[8 * ASTR + ks * 8 + 4]);
                        #pragma unroll
                        for (int qn = 0; qn < 4; qn++)
                            mma_tf32(c[qn], a0, a1, a2, a3,
                                     __float_as_uint(b[qn][ks].x), __float_as_uint(b[qn][ks].y));
                    }
                    const int e0 = mt * 16 + r0, e1 = e0 + 8;
                    #pragma unroll
                    for (int qn = 0; qn < 4; qn++) {
                        const int col = (nhalf * 4 + qn) * 8 + cq * 2;
                        if (e0 < rows) { acc[e0 * 65 + col] += c[qn][0]; acc[e0 * 65 + col + 1] += c[qn][1]; }
                        if (e1 < rows) { acc[e1 * 65 + col] += c[qn][2]; acc[e1 * 65 + col + 1] += c[qn][3]; }
                    }
                }
            } else {
                const int nv0 = nv[buf * 4 + 0], nv1 = nv[buf * 4 + 1];
                const int nv2 = nv[buf * 4 + 2], nv3 = nv[buf * 4 + 3];
                const int m0 = min(nv0, SEGCAP), m1 = min(nv1, SEGCAP);
                const int m2 = min(nv2, SEGCAP), m3 = min(nv3, SEGCAP);
                int mtx = max(max((m0 + 15) >> 4, (m1 + 15) >> 4),
                              max((m2 + 15) >> 4, (m3 + 15) >> 4));
                const int me = (klocal == 0) ? m0 : (klocal == 1) ? m1 : (klocal == 2) ? m2 : m3;
                const int mtiles_me = (me + 15) >> 4;
                const int j4me = (q - 1) * 4 + klocal;
                const int kgme = (j4me < 171) ? j4me : j4me + 1;

                float2 b[4][8];
                if (j4me < 342 && me > 0) {
                    const float2* Bf = (const float2*)(g_wB + (size_t)kgme * 4096);
                    #pragma unroll
                    for (int qn = 0; qn < 4; qn++)
                        #pragma unroll
                        for (int ks = 0; ks < 8; ks++)
                            b[qn][ks] = Bf[(ks * 8 + nhalf * 4 + qn) * 32 + lane];
                }
                const float* Ab = AB[buf];
                const int* vls = vl + (buf * 4 + klocal) * VLW;
                const int r0 = lane >> 2, cq = lane & 3;
                const int base = klocal * SEGCAP;

                for (int mt = 0; mt < mtx; mt++) {
                    float c[4][4];
                    const bool act = (mt < mtiles_me);
                    if (act) {
                        #pragma unroll
                        for (int qn = 0; qn < 4; qn++)
                            #pragma unroll
                            for (int u = 0; u < 4; u++) c[qn][u] = 0.f;
                        const float* Ap = Ab + (base + mt * 16 + r0) * ASTR + cq;
                        #pragma unroll
                        for (int ks = 0; ks < 8; ks++) {
                            uint32_t a0 = __float_as_uint(Ap[ks * 8]);
                            uint32_t a1 = __float_as_uint(Ap[8 * ASTR + ks * 8]);
                            uint32_t a2 = __float_as_uint(Ap[ks * 8 + 4]);
                            uint32_t a3 = __float_as_uint(Ap[8 * ASTR + ks * 8 + 4]);
                            #pragma unroll
                            for (int qn = 0; qn < 4; qn++)
                                mma_tf32(c[qn], a0, a1, a2, a3,
                                         __float_as_uint(b[qn][ks].x), __float_as_uint(b[qn][ks].y));
                        }
                    }
                    // k-ordered scatter windows (deterministic)
                    #pragma unroll
                    for (int j = 0; j < 4; j++) {
                        MBAR();
                        if (act && klocal == j) {
                            const int e0 = mt * 16 + r0, e1 = e0 + 8;
                            int v0 = (e0 < me) ? (vls[e0] >> 17) : -1;
                            int v1 = (e1 < me) ? (vls[e1] >> 17) : -1;
                            #pragma unroll
                            for (int qn = 0; qn < 4; qn++) {
                                const int col = (nhalf * 4 + qn) * 8 + cq * 2;
                                if (v0 >= 0) { acc[v0 * 65 + col] += c[qn][0]; acc[v0 * 65 + col + 1] += c[qn][1]; }
                                if (v1 >= 0) { acc[v1 * 65 + col] += c[qn][2]; acc[v1 * 65 + col + 1] += c[qn][3]; }
                            }
                        }
                    }
                }
                // rare overflow fallback (tf32-rounded FFMA, k-ordered)
                const bool ovany = (nv0 > SEGCAP) | (nv1 > SEGCAP) | (nv2 > SEGCAP) | (nv3 > SEGCAP);
                if (ovany) {
                    for (int j = 0; j < 4; j++) {
                        MBAR();
                        if (klocal == j) {
                            const int nvr = nv[buf * 4 + j];
                            const int hi = min(nvr, SEGCAP + OVCAP);
                            const int j4 = (q - 1) * 4 + j;
                            const int kg = (j4 < 171) ? j4 : j4 + 1;
                            const int cme = nhalf * 32 + lane;
                            for (int e = SEGCAP; e < hi; e++) {
                                int u = vl[(buf * 4 + j) * VLW + e];
                                int vv = u >> 17, n = u & 0x1FFFF;
                                const float* fr = feats + (size_t)n * 64;
                                const float* wr = w_dw + (size_t)kg * 4096 + cme;
                                float s = 0.f;
                                for (int ci = 0; ci < 64; ci++)
                                    s += tff(fr[ci]) * tff(wr[ci * 64]);
                                acc[vv * 65 + cme] += s;
                            }
                        }
                    }
                }
            }
        } else if (q < 86) {
            // producers: prepare buf^1 for phase q+1 (group phase q+1 covers j4=(q)*4+j)
            const int nbuf = buf ^ 1;
            float* Ab = AB[nbuf];
            if (ptid < 4) nv[nbuf * 4 + ptid] = 0;
            // stage sidx
            {
                const int v = ptid;
                int4 s4;
                const int gi = i0 + v;
                int j4b = q * 4;
                int n0 = NVOX, n1 = NVOX, n2 = NVOX, n3 = NVOX;
                if (v < rows) {
                    const int* row = nbr + (size_t)gi * KKTOT;
                    if (j4b + 0 < 342) { int k = j4b + 0; n0 = row[k < 171 ? k : k + 1]; }
                    if (j4b + 1 < 342) { int k = j4b + 1; n1 = row[k < 171 ? k : k + 1]; }
                    if (j4b + 2 < 342) { int k = j4b + 2; n2 = row[k < 171 ? k : k + 1]; }
                    if (j4b + 3 < 342) { int k = j4b + 3; n3 = row[k < 171 ? k : k + 1]; }
                }
                s4.x = n0; s4.y = n1; s4.z = n2; s4.w = n3;
                ((int4*)sidx)[v] = s4;
            }
            PBAR();
            // compact (warp-aggregated)
            {
                const int v = ptid;
                int4 s4 = ((int4*)sidx)[v];
                int ns[4] = { s4.x, s4.y, s4.z, s4.w };
                #pragma unroll
                for (int j = 0; j < 4; j++) {
                    bool valid = ns[j] < NVOX;
                    unsigned mask = __ballot_sync(0xFFFFFFFFu, valid);
                    int cnt = __popc(mask);
                    int rank = __popc(mask & ((1u << lane) - 1u));
                    int bbase = 0;
                    if (lane == 0 && cnt) bbase = atomicAdd(&nv[nbuf * 4 + j], cnt);
                    bbase = __shfl_sync(0xFFFFFFFFu, bbase, 0);
                    if (valid) {
                        int slot = bbase + rank;
                        if (slot < VLW) vl[(nbuf * 4 + j) * VLW + slot] = (v << 17) | ns[j];
                    }
                }
            }
            PBAR();
            // gather all segments
            const float4* f4g = (const float4*)feats;
            #pragma unroll
            for (int j = 0; j < 4; j++) {
                const int mj = min(nv[nbuf * 4 + j], SEGCAP);
                const int* vls = vl + (nbuf * 4 + j) * VLW;
                for (int t = ptid; t < mj * 16; t += 256) {
                    int e = t >> 4, pc = t & 15;
                    int n = vls[e] & 0x1FFFF;
                    float4 fv = f4g[(size_t)n * 16 + pc];
                    float4 o = make_float4(tff(fv.x), tff(fv.y), tff(fv.z), tff(fv.w));
                    *(float4*)(Ab + (j * SEGCAP + e) * ASTR + pc * 4) = o;
                }
            }
        }
        __syncthreads();
    }

    // ---- epilogue: bias, store g_x, GN partials ----
    const int v = tid >> 1;
    const int ch = (tid & 1) * 32;
    const int gi = i0 + v;
    const int b = bs[v];
    float s = 0.f, qq = 0.f, cnt = 0.f;
    if (v < rows) {
        float* dst = g_x + (size_t)gi * CDIM + ch;
        const float* ar = acc + v * 65 + ch;
        #pragma unroll
        for (int c = 0; c < 32; c += 4) {
            float x0 = ar[c + 0] + b_dw[ch + c + 0];
            float x1 = ar[c + 1] + b_dw[ch + c + 1];
            float x2 = ar[c + 2] + b_dw[ch + c + 2];
            float x3 = ar[c + 3] + b_dw[ch + c + 3];
            *(float4*)(dst + c) = make_float4(x0, x1, x2, x3);
            s += x0 + x1 + x2 + x3;
            qq += x0 * x0 + x1 * x1 + x2 * x2 + x3 * x3;
        }
        if ((tid & 1) == 0) cnt = 1.f;
    }
    __syncthreads();
    float* red = AB[0];
    red[0 * CNT + tid] = (b == 0) ? s : 0.f;
    red[1 * CNT + tid] = (b == 1) ? s : 0.f;
    red[2 * CNT + tid] = (b == 0) ? qq : 0.f;
    red[3 * CNT + tid] = (b == 1) ? qq : 0.f;
    red[4 * CNT + tid] = (b == 0) ? cnt : 0.f;
    red[5 * CNT + tid] = (b == 1) ? cnt : 0.f;
    __syncthreads();
    for (int off = CNT / 2; off > 0; off >>= 1) {
        if (tid < off) {
            #pragma unroll
            for (int a = 0; a < 6; a++) red[a * CNT + tid] += red[a * CNT + tid + off];
        }
        __syncthreads();
    }
    if (tid == 0) {
        float* pp = g_part1 + blockIdx.x * 8;
        #pragma unroll
        for (int a = 0; a < 6; a++) pp[a] = red[a * CNT];
    }
}

// ================= GN finalize =================
__global__ void __launch_bounds__(NT) gn_finalize() {
    __shared__ float red[8][32];
    const int t = threadIdx.x;
    const int comp = t & 7, stripe = t >> 3;
    float s = 0.f;
    if (comp < 6)
        for (int b = stripe; b < CBLK; b += 32) s += g_part1[b * 8 + comp];
    red[comp][stripe] = s;
    __syncthreads();
    if (t < 8) {
        float a = 0.f;
        #pragma unroll
        for (int i = 0; i < 32; i++) a += red[t][i];
        red[t][0] = a;
    }
    __syncthreads();
    if (t == 0) {
        double cnt0 = (double)red[4][0] * CDIM, cnt1 = (double)red[5][0] * CDIM;
        double m0 = (double)red[0][0] / cnt0, m1 = (double)red[1][0] / cnt1;
        double v0 = (double)red[2][0] / cnt0 - m0 * m0;
        double v1 = (double)red[3][0] / cnt1 - m1 * m1;
        g_gn[0] = (float)m0;
        g_gn[1] = (float)(1.0 / sqrt(v0 + 1e-6));
        g_gn[2] = (float)m1;
        g_gn[3] = (float)(1.0 / sqrt(v1 + 1e-6));
    }
}

// ================= pw1 =================
__global__ void __launch_bounds__(NT) pw1_kernel(
    const float* __restrict__ w_pw1,
    const float* __restrict__ gn_gamma,
    const float* __restrict__ gn_beta,
    const int*   __restrict__ batch_ids)
{
    extern __shared__ __align__(16) unsigned char smraw[];
    float* ws1 = (float*)smraw;
    float* xs  = ws1 + CDIM * C4;
    int*   bs  = (int*)(xs + PTILE * CDIM);

    const int tid = threadIdx.x;
    const int i0 = blockIdx.x * PTILE;
    const int rows = min(PTILE, NVOX - i0);
    const int j = tid;

    for (int t = tid; t < CDIM * C4; t += NT) ws1[t] = w_pw1[t];
    if (tid < PTILE) {
        int gi = i0 + tid;
        bs[tid] = (gi < NVOX) ? batch_ids[gi] : 0;
    }
    __syncthreads();
    const float mean0 = g_gn[0], rinv0 = g_gn[1], mean1 = g_gn[2], rinv1 = g_gn[3];
    for (int t = tid; t < PTILE * CDIM; t += NT) {
        int v = t >> 6, cc = t & 63;
        float xv = 0.f;
        if (v < rows) {
            int b = bs[v];
            float x = g_x[(size_t)(i0 + v) * CDIM + cc];
            float mn = (b == 0) ? mean0 : mean1;
            float ri = (b == 0) ? rinv0 : rinv1;
            xv = (x - mn) * ri * gn_gamma[cc] + gn_beta[cc];
        }
        xs[t] = xv;
    }
    __syncthreads();

    float pb0 = 0.f, pb1 = 0.f;
    for (int v0 = 0; v0 < PTILE; v0 += 8) {
        float s[8];
        #pragma unroll
        for (int r = 0; r < 8; r++) s[r] = 0.f;
        for (int cc = 0; cc < CDIM; cc += 4) {
            float w0 = ws1[(cc + 0) * C4 + j];
            float w1 = ws1[(cc + 1) * C4 + j];
            float w2 = ws1[(cc + 2) * C4 + j];
            float w3 = ws1[(cc + 3) * C4 + j];
            #pragma unroll
            for (int r = 0; r < 8; r++) {
                float4 a = *(const float4*)&xs[(v0 + r) * CDIM + cc];
                s[r] += a.x * w0 + a.y * w1 + a.z * w2 + a.w * w3;
            }
        }
        #pragma unroll
        for (int r = 0; r < 8; r++) {
            int v = v0 + r;
            if (v < rows) {
                float y = fmaxf(s[r], 0.f);
                g_y[(size_t)(i0 + v) * C4 + j] = y;
                if (bs[v] == 0) pb0 += y * y; else pb1 += y * y;
            }
        }
    }
    g_part2[blockIdx.x * (2 * C4) + j]      = pb0;
    g_part2[blockIdx.x * (2 * C4) + C4 + j] = pb1;
}

// ================= GRN stage1 + finalize =================
__global__ void __launch_bounds__(128) grn_stage1() {
    __shared__ float red[128];
    const int s = blockIdx.x;
    float a = 0.f;
    for (int b = threadIdx.x; b < PBLK; b += 128) a += g_part2[b * 512 + s];
    red[threadIdx.x] = a;
    __syncthreads();
    for (int off = 64; off > 0; off >>= 1) {
        if (threadIdx.x < off) red[threadIdx.x] += red[threadIdx.x + off];
        __syncthreads();
    }
    if (threadIdx.x == 0) g_gx2[s] = red[0];
}

__global__ void __launch_bounds__(C4) grn_finalize(
    const float* __restrict__ grn_gamma,
    const float* __restrict__ grn_beta,
    const float* __restrict__ w_pw2)
{
    __shared__ float r0[C4], r1[C4], bt[4][CDIM];
    const int j = threadIdx.x;
    float gx0 = sqrtf(g_gx2[j]);
    float gx1 = sqrtf(g_gx2[C4 + j]);
    r0[j] = gx0; r1[j] = gx1;
    __syncthreads();
    for (int off = C4 / 2; off > 0; off >>= 1) {
        if (j < off) { r0[j] += r0[j + off]; r1[j] += r1[j + off]; }
        __syncthreads();
    }
    float m0 = r0[0] / (float)C4;
    float m1 = r1[0] / (float)C4;
    float gam = grn_gamma[j];
    g_sj[j]      = 1.f + gam * (gx0 / (m0 + 1e-6f));
    g_sj[C4 + j] = 1.f + gam * (gx1 / (m1 + 1e-6f));
    const int part = j >> 6, jc = j & 63;
    float s = 0.f;
    for (int jj = part * 64; jj < part * 64 + 64; jj++)
        s += grn_beta[jj] * w_pw2[jj * CDIM + jc];
    bt[part][jc] = s;
    __syncthreads();
    if (j < CDIM) g_bterm[j] = bt[0][j] + bt[1][j] + bt[2][j] + bt[3][j];
}

// ================= pw2 =================
__global__ void __launch_bounds__(NT) pw2_kernel(
    const float* __restrict__ feats,
    const float* __restrict__ w_pw2,
    const int*   __restrict__ batch_ids,
    float* __restrict__ out)
{
    extern __shared__ __align__(16) unsigned char smraw[];
    float* ys  = (float*)smraw;
    float* w2s = ys + PTILE * CDIM;
    float* ssm = w2s + CDIM * CDIM;
    int*   bs  = (int*)(ssm + 2 * C4);

    const int tid = threadIdx.x;
    const int i0 = blockIdx.x * PTILE;
    const int rows = min(PTILE, NVOX - i0);
    const int c = tid & 63;
    const int g = tid >> 6;

    for (int t = tid; t < 2 * C4; t += NT) ssm[t] = g_sj[t];
    if (tid < PTILE) {
        int gi = i0 + tid;
        bs[tid] = (gi < NVOX) ? batch_ids[gi] : 0;
    }

    float accr[32];
    #pragma unroll
    for (int r = 0; r < 32; r++) accr[r] = 0.f;

    for (int jc = 0; jc < 4; jc++) {
        __syncthreads();
        for (int t = tid; t < CDIM * CDIM; t += NT)
            w2s[t] = w_pw2[(jc * CDIM + (t >> 6)) * CDIM + (t & 63)];
        for (int t = tid; t < PTILE * CDIM; t += NT) {
            int v = t >> 6, jj = t & 63;
            float y = 0.f;
            if (v < rows)
                y = g_y[(size_t)(i0 + v) * C4 + jc * CDIM + jj]
                    * ssm[bs[v] * C4 + jc * CDIM + jj];
            ys[t] = y;
        }
        __syncthreads();
        #pragma unroll
        for (int r = 0; r < 32; r += 2) {
            const float* y0 = ys + (g + 4 * r) * CDIM;
            const float* y1 = ys + (g + 4 * r + 4) * CDIM;
            float sA = accr[r], sB = accr[r + 1];
            #pragma unroll
            for (int jj = 0; jj < CDIM; jj += 4) {
                float w0 = w2s[(jj + 0) * CDIM + c];
                float w1 = w2s[(jj + 1) * CDIM + c];
                float w2 = w2s[(jj + 2) * CDIM + c];
                float w3 = w2s[(jj + 3) * CDIM + c];
                float4 a0 = *(const float4*)(y0 + jj);
                float4 a1 = *(const float4*)(y1 + jj);
                sA += a0.x * w0 + a0.y * w1 + a0.z * w2 + a0.w * w3;
                sB += a1.x * w0 + a1.y * w1 + a1.z * w2 + a1.w * w3;
            }
            accr[r] = sA; accr[r + 1] = sB;
        }
    }
    const float btv = g_bterm[c];
    #pragma unroll
    for (int r = 0; r < 32; r++) {
        int v = g + 4 * r;
        int gi = i0 + v;
        if (v < rows)
            out[(size_t)gi * CDIM + c] = feats[(size_t)gi * CDIM + c] + accr[r] + btv;
    }
}

// ================= launch =================
#define PW1_SMEM 99328
#define PW2_SMEM 52224

extern "C" void kernel_launch(void* const* d_in, const int* in_sizes, int n_in,
                              void* d_out, int out_size)
{
    const float* feats     = (const float*)d_in[0];
    const float* w_dw      = (const float*)d_in[1];
    const float* b_dw      = (const float*)d_in[2];
    const float* gn_gamma  = (const float*)d_in[3];
    const float* gn_beta   = (const float*)d_in[4];
    const float* w_pw1     = (const float*)d_in[5];
    const float* grn_gamma = (const float*)d_in[6];
    const float* grn_beta  = (const float*)d_in[7];
    const float* w_pw2     = (const float*)d_in[8];
    const int*   nbr       = (const int*)d_in[9];
    const int*   batch_ids = (const int*)d_in[10];
    float* out = (float*)d_out;

    cudaFuncSetAttribute(conv_kernel, cudaFuncAttributeMaxDynamicSharedMemorySize, CONV_SMEM);
    cudaFuncSetAttribute(pw1_kernel,  cudaFuncAttributeMaxDynamicSharedMemorySize, PW1_SMEM);
    cudaFuncSetAttribute(pw2_kernel,  cudaFuncAttributeMaxDynamicSharedMemorySize, PW2_SMEM);

    prep_wB<<<KKTOT, NT>>>(w_dw);
    conv_kernel<<<CBLK, CNT, CONV_SMEM>>>(feats, w_dw, b_dw, nbr, batch_ids);
    gn_finalize<<<1, NT>>>();
    pw1_kernel<<<PBLK, NT, PW1_SMEM>>>(w_pw1, gn_gamma, gn_beta, batch_ids);
    grn_stage1<<<512, 128>>>();
    grn_finalize<<<1, C4>>>(grn_gamma, grn_beta, w_pw2);
    pw2_kernel<<<PBLK, NT, PW2_SMEM>>>(feats, w_pw2, batch_ids, out);
}

// round 7
// speedup vs baseline: 2.8926x; 1.0820x over previous
#include <cuda_runtime.h>
#include <cstdint>
#include <math.h>

#define NVOX 100000
#define CDIM 64
#define C4   256
#define KKTOT 343
#define TILE 256
#define CNT  512
#define CBLK 391          // ceil(NVOX/256)
#define PTILE 128
#define PBLK 782
#define NT   256
#define ASTR 68
#define SEG  64

// ---------------- static scratch ----------------
__device__ float g_x[(size_t)NVOX * CDIM];
__device__ float g_y[(size_t)NVOX * C4];
__device__ float g_wB[(size_t)KKTOT * CDIM * CDIM];   // B fragment layout, tf32-rounded
__device__ float g_part1[CBLK * 8];
__device__ float g_part2[PBLK * 2 * C4];
__device__ float g_gx2[2 * C4];
__device__ float g_gn[4];
__device__ float g_sj[2 * C4];
__device__ float g_bterm[CDIM];

// ---------------- smem layout (bytes) ----------------
#define OFF_A0   0                      // 256*68*4 = 69632
#define OFF_A1   69632
#define OFF_STG  139264                 // 256*68*4 = 69632
#define OFF_VL   208896                 // 2*4*64*4 = 2048
#define OFF_INV  210944                 // 2*4*256  = 2048
#define OFF_NV   212992                 // 8*4 = 32
#define OFF_BS   213024                 // 1024
#define OFF_OVL  214048                 // 256*8 = 2048
#define OFF_OVN  216096                 // 4
#define OFF_BDW  216112                 // 256
#define CONV_SMEM 216576

__device__ __forceinline__ uint32_t f2tf32(float x) {
    uint32_t r;
    asm("cvt.rna.tf32.f32 %0, %1;" : "=r"(r) : "f"(x));
    return r;
}
__device__ __forceinline__ float tff(float x) { return __uint_as_float(f2tf32(x)); }

__device__ __forceinline__ void mma_tf32(float c[4], uint32_t a0, uint32_t a1,
                                         uint32_t a2, uint32_t a3,
                                         uint32_t b0, uint32_t b1) {
    asm volatile(
        "mma.sync.aligned.m16n8k8.row.col.f32.tf32.tf32.f32 "
        "{%0,%1,%2,%3}, {%4,%5,%6,%7}, {%8,%9}, {%0,%1,%2,%3};"
        : "+f"(c[0]), "+f"(c[1]), "+f"(c[2]), "+f"(c[3])
        : "r"(a0), "r"(a1), "r"(a2), "r"(a3), "r"(b0), "r"(b1));
}

#define PBAR() asm volatile("bar.sync 1, 256;" ::: "memory")
#define MBAR() asm volatile("bar.sync 2, 256;" ::: "memory")

// ================= prep: w_dw[k] -> B-fragment layout, tf32-rounded =================
__global__ void __launch_bounds__(NT) prep_wB(const float* __restrict__ w_dw) {
    const int k = blockIdx.x;
    const float* wk = w_dw + (size_t)k * 4096;
    float* dst = g_wB + (size_t)k * 4096;
    for (int t = threadIdx.x; t < 4096; t += NT) {
        int cin = t >> 6, cout = t & 63;
        int kstep = cin >> 3, kk = cin & 7;
        int nt = cout >> 3, nn = cout & 7;
        int idx = (((kstep * 8 + nt) * 32 + nn * 4 + (kk & 3)) << 1) + (kk >> 2);
        dst[idx] = __uint_as_float(f2tf32(wk[t]));
    }
}

// ================= conv: register accumulator + staging merge =================
__global__ void __launch_bounds__(CNT, 1) conv_kernel(
    const float* __restrict__ feats,
    const float* __restrict__ w_dw,
    const float* __restrict__ b_dw,
    const int*   __restrict__ nbr,
    const int*   __restrict__ batch_ids)
{
    extern __shared__ __align__(16) unsigned char smraw[];
    float* A[2] = { (float*)(smraw + OFF_A0), (float*)(smraw + OFF_A1) };
    float* stg  = (float*)(smraw + OFF_STG);
    int* vl     = (int*)(smraw + OFF_VL);
    unsigned char* inv = (unsigned char*)(smraw + OFF_INV);
    int* nv     = (int*)(smraw + OFF_NV);
    int* bs     = (int*)(smraw + OFF_BS);
    int* ovl    = (int*)(smraw + OFF_OVL);
    int* ovn    = (int*)(smraw + OFF_OVN);
    float* bdw  = (float*)(smraw + OFF_BDW);

    const int tid  = threadIdx.x;
    const int lane = tid & 31;
    const int warp = tid >> 5;
    const int i0   = blockIdx.x * TILE;
    const int rows = min(TILE, NVOX - i0);
    const bool isOwn = tid < 256;
    const int ptid = tid - 256;

    float acc[64];
    if (isOwn) {
        #pragma unroll
        for (int c = 0; c < 64; c++) acc[c] = 0.f;
    }
    if (tid < TILE) bs[tid] = (tid < rows) ? batch_ids[i0 + tid] : -1;
    if (tid == 0) *ovn = 0;
    if (tid < 64) bdw[tid] = b_dw[tid];

    // prologue: producers fill A[0] with self rows; identity lists for center phase
    if (!isOwn) {
        ((uint32_t*)inv)[ptid] = 0xFFFFFFFFu;                  // clear inv[buf0]
        if (ptid < 4) nv[ptid] = max(0, min(rows - ptid * 64, 64));
        PBAR();
        if (ptid < rows) inv[(ptid >> 6) * 256 + ptid] = (unsigned char)(ptid & 63);
        const float4* f4g = (const float4*)feats;
        for (int t = ptid; t < rows * 16; t += 256) {
            int v = t >> 4, pc = t & 15;
            float4 fv = f4g[(size_t)(i0 + v) * 16 + pc];
            *(float4*)(A[0] + v * ASTR + pc * 4) =
                make_float4(tff(fv.x), tff(fv.y), tff(fv.z), tff(fv.w));
        }
    }
    __syncthreads();

    // phases: q=0 center k=171 (identity segs), q=1..86 groups of 4 non-center ks
    for (int q = 0; q <= 86; q++) {
        const int buf = q & 1;
        if (isOwn) {
            const int jme = warp >> 1, nh = warp & 1;
            int kg;
            if (q == 0) kg = 171;
            else { int j4 = (q - 1) * 4 + jme; kg = (j4 < 342) ? (j4 < 171 ? j4 : j4 + 1) : -1; }
            const int m = (kg >= 0) ? min(nv[buf * 4 + jme], SEG) : 0;
            const int mtc = (m + 15) >> 4;
            const float* Ab = A[buf] + jme * SEG * ASTR;
            const float2* Bf = (const float2*)(g_wB + (size_t)max(kg, 0) * 4096);
            const int r0 = lane >> 2, cq = lane & 3;

            #pragma unroll
            for (int p = 0; p < 2; p++) {
                const int oct0 = nh * 4 + 2 * p;
                float2 b0[8], b1[8];
                if (m > 0) {
                    #pragma unroll
                    for (int ks = 0; ks < 8; ks++) {
                        b0[ks] = Bf[(ks * 8 + oct0) * 32 + lane];
                        b1[ks] = Bf[(ks * 8 + oct0 + 1) * 32 + lane];
                    }
                }
                for (int mt = 0; mt < mtc; mt++) {
                    float c0[4] = {0.f, 0.f, 0.f, 0.f};
                    float c1[4] = {0.f, 0.f, 0.f, 0.f};
                    const float* Ap = Ab + (mt * 16 + r0) * ASTR + cq;
                    #pragma unroll
                    for (int ks = 0; ks < 8; ks++) {
                        uint32_t a0 = __float_as_uint(Ap[ks * 8]);
                        uint32_t a1 = __float_as_uint(Ap[8 * ASTR + ks * 8]);
                        uint32_t a2 = __float_as_uint(Ap[ks * 8 + 4]);
                        uint32_t a3 = __float_as_uint(Ap[8 * ASTR + ks * 8 + 4]);
                        mma_tf32(c0, a0, a1, a2, a3,
                                 __float_as_uint(b0[ks].x), __float_as_uint(b0[ks].y));
                        mma_tf32(c1, a0, a1, a2, a3,
                                 __float_as_uint(b1[ks].x), __float_as_uint(b1[ks].y));
                    }
                    float* st = stg + (jme * SEG + mt * 16 + r0) * ASTR + oct0 * 8 + cq * 2;
                    *(float2*)(st)               = make_float2(c0[0], c0[1]);
                    *(float2*)(st + 8)           = make_float2(c1[0], c1[1]);
                    *(float2*)(st + 8 * ASTR)     = make_float2(c0[2], c0[3]);
                    *(float2*)(st + 8 * ASTR + 8) = make_float2(c1[2], c1[3]);
                }
            }
            MBAR();
            // merge staged rows into register accumulator (deterministic j order)
            if (tid < rows) {
                #pragma unroll
                for (int j = 0; j < 4; j++) {
                    unsigned e = inv[buf * 1024 + j * 256 + tid];
                    if (e != 0xFFu) {
                        const float4* sr = (const float4*)(stg + (j * SEG + (int)e) * ASTR);
                        #pragma unroll
                        for (int c4 = 0; c4 < 16; c4++) {
                            float4 t = sr[c4];
                            acc[4 * c4 + 0] += t.x;
                            acc[4 * c4 + 1] += t.y;
                            acc[4 * c4 + 2] += t.z;
                            acc[4 * c4 + 3] += t.w;
                        }
                    }
                }
            }
        } else if (q < 86) {
            const int nbuf = buf ^ 1;
            ((uint32_t*)inv)[nbuf * 256 + ptid] = 0xFFFFFFFFu;
            if (ptid < 4) nv[nbuf * 4 + ptid] = 0;
            int ns[4];
            {
                const int v = ptid;
                if (v < rows) {
                    const int* rowp = nbr + (size_t)(i0 + v) * KKTOT;
                    #pragma unroll
                    for (int j = 0; j < 4; j++) {
                        int j4 = q * 4 + j;
                        ns[j] = (j4 < 342) ? rowp[j4 < 171 ? j4 : j4 + 1] : NVOX;
                    }
                } else {
                    #pragma unroll
                    for (int j = 0; j < 4; j++) ns[j] = NVOX;
                }
            }
            PBAR();
            #pragma unroll
            for (int j = 0; j < 4; j++) {
                bool valid = ns[j] < NVOX;
                unsigned mask = __ballot_sync(0xFFFFFFFFu, valid);
                int cnt = __popc(mask);
                int rank = __popc(mask & ((1u << lane) - 1u));
                int bbase = 0;
                if (lane == 0 && cnt) bbase = atomicAdd(&nv[nbuf * 4 + j], cnt);
                bbase = __shfl_sync(0xFFFFFFFFu, bbase, 0);
                if (valid) {
                    int slot = bbase + rank;
                    if (slot < SEG) {
                        vl[(nbuf * 4 + j) * SEG + slot] = (ptid << 17) | ns[j];
                        inv[nbuf * 1024 + j * 256 + ptid] = (unsigned char)slot;
                    } else {
                        int oi = atomicAdd(ovn, 1);
                        if (oi < 256) { ovl[oi * 2] = (ptid << 17) | ns[j]; ovl[oi * 2 + 1] = q * 4 + j; }
                    }
                }
            }
            PBAR();
            float* Ab = A[nbuf];
            const float4* f4g = (const float4*)feats;
            #pragma unroll
            for (int j = 0; j < 4; j++) {
                const int mj = min(nv[nbuf * 4 + j], SEG);
                const int* vls = vl + (nbuf * 4 + j) * SEG;
                for (int t = ptid; t < mj * 16; t += 256) {
                    int e = t >> 4, pc = t & 15;
                    int n = vls[e] & 0x1FFFF;
                    float4 fv = f4g[(size_t)n * 16 + pc];
                    *(float4*)(Ab + (j * SEG + e) * ASTR + pc * 4) =
                        make_float4(tff(fv.x), tff(fv.y), tff(fv.z), tff(fv.w));
                }
            }
        }
        __syncthreads();
    }

    // ---- overflow handling (rare): stage each entry cooperatively, merge j-sorted ----
    const int ncnt = min(*ovn, 256);
    if (ncnt > 0) {
        for (int base = 0; base < ncnt; base += 8) {
            int e = base + (tid >> 6);
            if (e < ncnt) {
                int u = ovl[e * 2], j4 = ovl[e * 2 + 1];
                int n = u & 0x1FFFF;
                int kg = (j4 < 171) ? j4 : j4 + 1;
                int c = tid & 63;
                const float* fr = feats + (size_t)n * 64;
                const float* wr = w_dw + (size_t)kg * 4096 + c;
                float s = 0.f;
                for (int ci = 0; ci < 64; ci++) s += tff(fr[ci]) * tff(wr[ci * 64]);
                stg[e * ASTR + c] = s;
            }
        }
        __syncthreads();
        if (isOwn && tid < rows) {
            int done = -1;
            while (true) {
                int best = 1 << 30, bi = -1;
                for (int e2 = 0; e2 < ncnt; e2++) {
                    if ((ovl[e2 * 2] >> 17) == tid) {
                        int j4 = ovl[e2 * 2 + 1];
                        if (j4 > done && j4 < best) { best = j4; bi = e2; }
                    }
                }
                if (bi < 0) break;
                const float4* sr = (const float4*)(stg + bi * ASTR);
                #pragma unroll
                for (int c4 = 0; c4 < 16; c4++) {
                    float4 t = sr[c4];
                    acc[4 * c4 + 0] += t.x;
                    acc[4 * c4 + 1] += t.y;
                    acc[4 * c4 + 2] += t.z;
                    acc[4 * c4 + 3] += t.w;
                }
                done = best;
            }
        }
        __syncthreads();
    }

    // ---- epilogue: bias, store g_x, GN partials ----
    float s = 0.f, qq = 0.f, cnt = 0.f;
    int b = -1;
    if (isOwn) {
        b = bs[tid];
        if (tid < rows) {
            float* dst = g_x + (size_t)(i0 + tid) * CDIM;
            #pragma unroll
            for (int c4 = 0; c4 < 16; c4++) {
                float x0 = acc[4 * c4 + 0] + bdw[4 * c4 + 0];
                float x1 = acc[4 * c4 + 1] + bdw[4 * c4 + 1];
                float x2 = acc[4 * c4 + 2] + bdw[4 * c4 + 2];
                float x3 = acc[4 * c4 + 3] + bdw[4 * c4 + 3];
                *(float4*)(dst + 4 * c4) = make_float4(x0, x1, x2, x3);
                s += x0 + x1 + x2 + x3;
                qq += x0 * x0 + x1 * x1 + x2 * x2 + x3 * x3;
            }
            cnt = 1.f;
        }
    }
    __syncthreads();
    float* red = (float*)smraw;
    red[0 * CNT + tid] = (b == 0) ? s : 0.f;
    red[1 * CNT + tid] = (b == 1) ? s : 0.f;
    red[2 * CNT + tid] = (b == 0) ? qq : 0.f;
    red[3 * CNT + tid] = (b == 1) ? qq : 0.f;
    red[4 * CNT + tid] = (b == 0) ? cnt : 0.f;
    red[5 * CNT + tid] = (b == 1) ? cnt : 0.f;
    __syncthreads();
    for (int off = CNT / 2; off > 0; off >>= 1) {
        if (tid < off) {
            #pragma unroll
            for (int a = 0; a < 6; a++) red[a * CNT + tid] += red[a * CNT + tid + off];
        }
        __syncthreads();
    }
    if (tid == 0) {
        float* pp = g_part1 + blockIdx.x * 8;
        #pragma unroll
        for (int a = 0; a < 6; a++) pp[a] = red[a * CNT];
    }
}

// ================= GN finalize =================
__global__ void __launch_bounds__(NT) gn_finalize() {
    __shared__ float red[8][32];
    const int t = threadIdx.x;
    const int comp = t & 7, stripe = t >> 3;
    float s = 0.f;
    if (comp < 6)
        for (int b = stripe; b < CBLK; b += 32) s += g_part1[b * 8 + comp];
    red[comp][stripe] = s;
    __syncthreads();
    if (t < 8) {
        float a = 0.f;
        #pragma unroll
        for (int i = 0; i < 32; i++) a += red[t][i];
        red[t][0] = a;
    }
    __syncthreads();
    if (t == 0) {
        double cnt0 = (double)red[4][0] * CDIM, cnt1 = (double)red[5][0] * CDIM;
        double m0 = (double)red[0][0] / cnt0, m1 = (double)red[1][0] / cnt1;
        double v0 = (double)red[2][0] / cnt0 - m0 * m0;
        double v1 = (double)red[3][0] / cnt1 - m1 * m1;
        g_gn[0] = (float)m0;
        g_gn[1] = (float)(1.0 / sqrt(v0 + 1e-6));
        g_gn[2] = (float)m1;
        g_gn[3] = (float)(1.0 / sqrt(v1 + 1e-6));
    }
}

// ================= pw1 =================
__global__ void __launch_bounds__(NT) pw1_kernel(
    const float* __restrict__ w_pw1,
    const float* __restrict__ gn_gamma,
    const float* __restrict__ gn_beta,
    const int*   __restrict__ batch_ids)
{
    extern __shared__ __align__(16) unsigned char smraw[];
    float* ws1 = (float*)smraw;
    float* xs  = ws1 + CDIM * C4;
    int*   bs  = (int*)(xs + PTILE * CDIM);

    const int tid = threadIdx.x;
    const int i0 = blockIdx.x * PTILE;
    const int rows = min(PTILE, NVOX - i0);
    const int j = tid;

    for (int t = tid; t < CDIM * C4; t += NT) ws1[t] = w_pw1[t];
    if (tid < PTILE) {
        int gi = i0 + tid;
        bs[tid] = (gi < NVOX) ? batch_ids[gi] : 0;
    }
    __syncthreads();
    const float mean0 = g_gn[0], rinv0 = g_gn[1], mean1 = g_gn[2], rinv1 = g_gn[3];
    for (int t = tid; t < PTILE * CDIM; t += NT) {
        int v = t >> 6, cc = t & 63;
        float xv = 0.f;
        if (v < rows) {
            int b = bs[v];
            float x = g_x[(size_t)(i0 + v) * CDIM + cc];
            float mn = (b == 0) ? mean0 : mean1;
            float ri = (b == 0) ? rinv0 : rinv1;
            xv = (x - mn) * ri * gn_gamma[cc] + gn_beta[cc];
        }
        xs[t] = xv;
    }
    __syncthreads();

    float pb0 = 0.f, pb1 = 0.f;
    for (int v0 = 0; v0 < PTILE; v0 += 8) {
        float s[8];
        #pragma unroll
        for (int r = 0; r < 8; r++) s[r] = 0.f;
        for (int cc = 0; cc < CDIM; cc += 4) {
            float w0 = ws1[(cc + 0) * C4 + j];
            float w1 = ws1[(cc + 1) * C4 + j];
            float w2 = ws1[(cc + 2) * C4 + j];
            float w3 = ws1[(cc + 3) * C4 + j];
            #pragma unroll
            for (int r = 0; r < 8; r++) {
                float4 a = *(const float4*)&xs[(v0 + r) * CDIM + cc];
                s[r] += a.x * w0 + a.y * w1 + a.z * w2 + a.w * w3;
            }
        }
        #pragma unroll
        for (int r = 0; r < 8; r++) {
            int v = v0 + r;
            if (v < rows) {
                float y = fmaxf(s[r], 0.f);
                g_y[(size_t)(i0 + v) * C4 + j] = y;
                if (bs[v] == 0) pb0 += y * y; else pb1 += y * y;
            }
        }
    }
    g_part2[blockIdx.x * (2 * C4) + j]      = pb0;
    g_part2[blockIdx.x * (2 * C4) + C4 + j] = pb1;
}

// ================= GRN stage1 + finalize =================
__global__ void __launch_bounds__(128) grn_stage1() {
    __shared__ float red[128];
    const int s = blockIdx.x;
    float a = 0.f;
    for (int b = threadIdx.x; b < PBLK; b += 128) a += g_part2[b * 512 + s];
    red[threadIdx.x] = a;
    __syncthreads();
    for (int off = 64; off > 0; off >>= 1) {
        if (threadIdx.x < off) red[threadIdx.x] += red[threadIdx.x + off];
        __syncthreads();
    }
    if (threadIdx.x == 0) g_gx2[s] = red[0];
}

__global__ void __launch_bounds__(C4) grn_finalize(
    const float* __restrict__ grn_gamma,
    const float* __restrict__ grn_beta,
    const float* __restrict__ w_pw2)
{
    __shared__ float r0[C4], r1[C4], bt[4][CDIM];
    const int j = threadIdx.x;
    float gx0 = sqrtf(g_gx2[j]);
    float gx1 = sqrtf(g_gx2[C4 + j]);
    r0[j] = gx0; r1[j] = gx1;
    __syncthreads();
    for (int off = C4 / 2; off > 0; off >>= 1) {
        if (j < off) { r0[j] += r0[j + off]; r1[j] += r1[j + off]; }
        __syncthreads();
    }
    float m0 = r0[0] / (float)C4;
    float m1 = r1[0] / (float)C4;
    float gam = grn_gamma[j];
    g_sj[j]      = 1.f + gam * (gx0 / (m0 + 1e-6f));
    g_sj[C4 + j] = 1.f + gam * (gx1 / (m1 + 1e-6f));
    const int part = j >> 6, jc = j & 63;
    float s = 0.f;
    for (int jj = part * 64; jj < part * 64 + 64; jj++)
        s += grn_beta[jj] * w_pw2[jj * CDIM + jc];
    bt[part][jc] = s;
    __syncthreads();
    if (j < CDIM) g_bterm[j] = bt[0][j] + bt[1][j] + bt[2][j] + bt[3][j];
}

// ================= pw2 =================
__global__ void __launch_bounds__(NT) pw2_kernel(
    const float* __restrict__ feats,
    const float* __restrict__ w_pw2,
    const int*   __restrict__ batch_ids,
    float* __restrict__ out)
{
    extern __shared__ __align__(16) unsigned char smraw[];
    float* ys  = (float*)smraw;
    float* w2s = ys + PTILE * CDIM;
    float* ssm = w2s + CDIM * CDIM;
    int*   bs  = (int*)(ssm + 2 * C4);

    const int tid = threadIdx.x;
    const int i0 = blockIdx.x * PTILE;
    const int rows = min(PTILE, NVOX - i0);
    const int c = tid & 63;
    const int g = tid >> 6;

    for (int t = tid; t < 2 * C4; t += NT) ssm[t] = g_sj[t];
    if (tid < PTILE) {
        int gi = i0 + tid;
        bs[tid] = (gi < NVOX) ? batch_ids[gi] : 0;
    }

    float accr[32];
    #pragma unroll
    for (int r = 0; r < 32; r++) accr[r] = 0.f;

    for (int jc = 0; jc < 4; jc++) {
        __syncthreads();
        for (int t = tid; t < CDIM * CDIM; t += NT)
            w2s[t] = w_pw2[(jc * CDIM + (t >> 6)) * CDIM + (t & 63)];
        for (int t = tid; t < PTILE * CDIM; t += NT) {
            int v = t >> 6, jj = t & 63;
            float y = 0.f;
            if (v < rows)
                y = g_y[(size_t)(i0 + v) * C4 + jc * CDIM + jj]
                    * ssm[bs[v] * C4 + jc * CDIM + jj];
            ys[t] = y;
        }
        __syncthreads();
        #pragma unroll
        for (int r = 0; r < 32; r += 2) {
            const float* y0 = ys + (g + 4 * r) * CDIM;
            const float* y1 = ys + (g + 4 * r + 4) * CDIM;
            float sA = accr[r], sB = accr[r + 1];
            #pragma unroll
            for (int jj = 0; jj < CDIM; jj += 4) {
                float w0 = w2s[(jj + 0) * CDIM + c];
                float w1 = w2s[(jj + 1) * CDIM + c];
                float w2 = w2s[(jj + 2) * CDIM + c];
                float w3 = w2s[(jj + 3) * CDIM + c];
                float4 a0 = *(const float4*)(y0 + jj);
                float4 a1 = *(const float4*)(y1 + jj);
                sA += a0.x * w0 + a0.y * w1 + a0.z * w2 + a0.w * w3;
                sB += a1.x * w0 + a1.y * w1 + a1.z * w2 + a1.w * w3;
            }
            accr[r] = sA; accr[r + 1] = sB;
        }
    }
    const float btv = g_bterm[c];
    #pragma unroll
    for (int r = 0; r < 32; r++) {
        int v = g + 4 * r;
        int gi = i0 + v;
        if (v < rows)
            out[(size_t)gi * CDIM + c] = feats[(size_t)gi * CDIM + c] + accr[r] + btv;
    }
}

// ================= launch =================
#define PW1_SMEM 99328
#define PW2_SMEM 52224

extern "C" void kernel_launch(void* const* d_in, const int* in_sizes, int n_in,
                              void* d_out, int out_size)
{
    const float* feats     = (const float*)d_in[0];
    const float* w_dw      = (const float*)d_in[1];
    const float* b_dw      = (const float*)d_in[2];
    const float* gn_gamma  = (const float*)d_in[3];
    const float* gn_beta   = (const float*)d_in[4];
    const float* w_pw1     = (const float*)d_in[5];
    const float* grn_gamma = (const float*)d_in[6];
    const float* grn_beta  = (const float*)d_in[7];
    const float* w_pw2     = (const float*)d_in[8];
    const int*   nbr       = (const int*)d_in[9];
    const int*   batch_ids = (const int*)d_in[10];
    float* out = (float*)d_out;

    cudaFuncSetAttribute(conv_kernel, cudaFuncAttributeMaxDynamicSharedMemorySize, CONV_SMEM);
    cudaFuncSetAttribute(pw1_kernel,  cudaFuncAttributeMaxDynamicSharedMemorySize, PW1_SMEM);
    cudaFuncSetAttribute(pw2_kernel,  cudaFuncAttributeMaxDynamicSharedMemorySize, PW2_SMEM);

    prep_wB<<<KKTOT, NT>>>(w_dw);
    conv_kernel<<<CBLK, CNT, CONV_SMEM>>>(feats, w_dw, b_dw, nbr, batch_ids);
    gn_finalize<<<1, NT>>>();
    pw1_kernel<<<PBLK, NT, PW1_SMEM>>>(w_pw1, gn_gamma, gn_beta, batch_ids);
    grn_stage1<<<512, 128>>>();
    grn_finalize<<<1, C4>>>(grn_gamma, grn_beta, w_pw2);
    pw2_kernel<<<PBLK, NT, PW2_SMEM>>>(feats, w_pw2, batch_ids, out);
}